// round 3
// baseline (speedup 1.0000x reference)
#include <cuda_runtime.h>
#include <math.h>

#define BATCH   16
#define SEQ     2048
#define DIN     128
#define HIDDEN  512
#define STATE   256
#define DOUT    64
#define NLAYERS 4
#define MROWS   (BATCH * SEQ)   /* 32768 */

// ---------------- scratch (allocation-free: __device__ globals) ----------------
__device__ float g_bufh[(size_t)MROWS * HIDDEN];   // residual stream h
__device__ float g_bufa[(size_t)MROWS * HIDDEN];   // Bu / y
__device__ float g_bufb[(size_t)MROWS * HIDDEN];   // scan out / u
__device__ float g_Bn [2 * STATE * HIDDEN];        // stacked [B_re*e^g ; B_im*e^g]  (2S, H)
__device__ float g_Wc [HIDDEN * 2 * STATE];        // stacked [C_re | -C_im]         (H, 2S)
__device__ float g_lam[2 * STATE];                 // lambda re, im

// ---------------- per-layer small precompute ----------------
__global__ void prep_kernel(const float* __restrict__ nu, const float* __restrict__ th,
                            const float* __restrict__ ga,
                            const float* __restrict__ Bre, const float* __restrict__ Bim,
                            const float* __restrict__ Cre, const float* __restrict__ Cim)
{
    int tid = blockIdx.x * blockDim.x + threadIdx.x;
    int stride = gridDim.x * blockDim.x;

    if (tid < STATE) {
        float mag = expf(-expf(nu[tid]));
        float ang = expf(th[tid]);
        g_lam[tid]         = mag * cosf(ang);
        g_lam[STATE + tid] = mag * sinf(ang);
    }
    // Bn: (2S, H)
    for (int idx = tid; idx < STATE * HIDDEN; idx += stride) {
        int s = idx / HIDDEN;
        float g = expf(ga[s]);
        g_Bn[idx]                  = Bre[idx] * g;
        g_Bn[STATE * HIDDEN + idx] = Bim[idx] * g;
    }
    // Wc: (H, 2S)
    for (int idx = tid; idx < HIDDEN * STATE; idx += stride) {
        int h = idx / STATE, s = idx % STATE;
        g_Wc[h * (2 * STATE) + s]         =  Cre[idx];
        g_Wc[h * (2 * STATE) + STATE + s] = -Cim[idx];
    }
}

// ---------------- diagonal complex scan ----------------
// Bu layout: row m = b*SEQ + t, cols [0..S) = re, [S..2S) = im
__global__ void scan_kernel(const float* __restrict__ Bu, float* __restrict__ Hs)
{
    int t = blockIdx.x * blockDim.x + threadIdx.x;      // 0 .. BATCH*STATE-1
    int b = t / STATE;
    int s = t % STATE;
    float lr = g_lam[s], li = g_lam[STATE + s];
    size_t base = (size_t)b * SEQ * (2 * STATE) + s;
    float hr = 0.f, hi = 0.f;
#pragma unroll 4
    for (int i = 0; i < SEQ; i++) {
        size_t off = base + (size_t)i * (2 * STATE);
        float br = Bu[off], bi = Bu[off + STATE];
        float nr = fmaf(lr, hr, fmaf(-li, hi, br));
        float ni = fmaf(lr, hi, fmaf( li, hr, bi));
        hr = nr; hi = ni;
        Hs[off] = hr; Hs[off + STATE] = hi;
    }
}

// ---------------- tiled fp32 GEMM: C[M,N] = A[M,K] @ W[N,K]^T  (+ epilogue) ----------------
// EPI 0: C = acc (+bias)
// EPI 1: v = acc + e1[m]*e2[col]; C = gelu_exact(v)           (bias unused)
// EPI 2: v = acc + bias[col]; C = e1[m]*sigmoid(v) + e2[m]    (GLU + residual)
template <int BN_, int TN_, int EPI>
__global__ void __launch_bounds__(256, 2)
sgemm_kernel(const float* __restrict__ A, const float* __restrict__ W,
             const float* __restrict__ bias, float* __restrict__ C,
             int M, int N, int K,
             const float* __restrict__ e1, const float* __restrict__ e2)
{
    constexpr int BM = 128, BK = 8, TM = 8;
    constexpr int THREADS = (BM / TM) * (BN_ / TN_);   // 256 for both instantiations

    __shared__ float As[BK][BM];
    __shared__ float Ws[BK][BN_];

    int tid = threadIdx.x;
    int block_m = blockIdx.y * BM;
    int block_n = blockIdx.x * BN_;
    int trow = tid / (BN_ / TN_);
    int tcol = tid % (BN_ / TN_);

    float acc[TM][TN_];
#pragma unroll
    for (int i = 0; i < TM; i++)
#pragma unroll
        for (int j = 0; j < TN_; j++) acc[i][j] = 0.f;

    for (int k0 = 0; k0 < K; k0 += BK) {
        // load A tile (BM x BK): 1024 floats / 256 thr = one float4 each
        {
            int f = tid * 4;
            int r = f / BK, c = f % BK;
            float4 v = *reinterpret_cast<const float4*>(&A[(size_t)(block_m + r) * K + k0 + c]);
            As[c + 0][r] = v.x; As[c + 1][r] = v.y; As[c + 2][r] = v.z; As[c + 3][r] = v.w;
        }
        // load W tile (BN_ x BK)
        for (int f = tid * 4; f < BN_ * BK; f += THREADS * 4) {
            int r = f / BK, c = f % BK;
            float4 v = *reinterpret_cast<const float4*>(&W[(size_t)(block_n + r) * K + k0 + c]);
            Ws[c + 0][r] = v.x; Ws[c + 1][r] = v.y; Ws[c + 2][r] = v.z; Ws[c + 3][r] = v.w;
        }
        __syncthreads();

#pragma unroll
        for (int k = 0; k < BK; k++) {
            float a[TM], w[TN_];
#pragma unroll
            for (int i = 0; i < TM; i += 4) {
                float4 v = *reinterpret_cast<const float4*>(&As[k][trow * TM + i]);
                a[i] = v.x; a[i + 1] = v.y; a[i + 2] = v.z; a[i + 3] = v.w;
            }
#pragma unroll
            for (int j = 0; j < TN_; j += 4) {
                float4 v = *reinterpret_cast<const float4*>(&Ws[k][tcol * TN_ + j]);
                w[j] = v.x; w[j + 1] = v.y; w[j + 2] = v.z; w[j + 3] = v.w;
            }
#pragma unroll
            for (int i = 0; i < TM; i++)
#pragma unroll
                for (int j = 0; j < TN_; j++)
                    acc[i][j] = fmaf(a[i], w[j], acc[i][j]);
        }
        __syncthreads();
    }

#pragma unroll
    for (int i = 0; i < TM; i++) {
        int row = block_m + trow * TM + i;
#pragma unroll
        for (int j = 0; j < TN_; j++) {
            int col = block_n + tcol * TN_ + j;
            size_t o = (size_t)row * N + col;
            float v = acc[i][j];
            if (EPI == 0) {
                if (bias) v += bias[col];
                C[o] = v;
            } else if (EPI == 1) {
                v += e1[o] * e2[col];
                C[o] = v * normcdff(v);          // exact GELU
            } else {
                v += bias[col];
                float s = 1.f / (1.f + expf(-v));
                C[o] = fmaf(e1[o], s, e2[o]);    // u * sigmoid(g) + residual
            }
        }
    }
}

// ---------------- launcher ----------------
extern "C" void kernel_launch(void* const* d_in, const int* in_sizes, int n_in,
                              void* d_out, int out_size)
{
    const float* x    = (const float*)d_in[0];
    const float* embW = (const float*)d_in[1];
    const float* embb = (const float*)d_in[2];
    const float* nu   = (const float*)d_in[3];
    const float* th   = (const float*)d_in[4];
    const float* ga   = (const float*)d_in[5];
    const float* Bre  = (const float*)d_in[6];
    const float* Bim  = (const float*)d_in[7];
    const float* Cre  = (const float*)d_in[8];
    const float* Cim  = (const float*)d_in[9];
    const float* Dv   = (const float*)d_in[10];
    const float* W1   = (const float*)d_in[11];
    const float* b1   = (const float*)d_in[12];
    const float* W2   = (const float*)d_in[13];
    const float* b2   = (const float*)d_in[14];
    const float* outW = (const float*)d_in[15];
    const float* outb = (const float*)d_in[16];
    float* out = (float*)d_out;
    (void)in_sizes; (void)n_in; (void)out_size;

    float *bufh, *bufa, *bufb, *Bn, *Wc;
    cudaGetSymbolAddress((void**)&bufh, g_bufh);
    cudaGetSymbolAddress((void**)&bufa, g_bufa);
    cudaGetSymbolAddress((void**)&bufb, g_bufb);
    cudaGetSymbolAddress((void**)&Bn,  g_Bn);
    cudaGetSymbolAddress((void**)&Wc,  g_Wc);

    const int M = MROWS;
    dim3 blk(256);
    dim3 g512(HIDDEN / 128, M / 128);     // N=512 GEMMs
    dim3 gout(1, M / 128);                // N=64 output GEMM

    // embedding: h = x @ embW^T + embb
    sgemm_kernel<128, 8, 0><<<g512, blk>>>(x, embW, embb, bufh, M, HIDDEN, DIN,
                                           nullptr, nullptr);

    for (int l = 0; l < NLAYERS; l++) {
        prep_kernel<<<128, 256>>>(nu + l * STATE, th + l * STATE, ga + l * STATE,
                                  Bre + (size_t)l * STATE * HIDDEN,
                                  Bim + (size_t)l * STATE * HIDDEN,
                                  Cre + (size_t)l * HIDDEN * STATE,
                                  Cim + (size_t)l * HIDDEN * STATE);

        // Bu = h @ [Bn_re; Bn_im]^T   -> bufa  (M x 2S)
        sgemm_kernel<128, 8, 0><<<g512, blk>>>(bufh, Bn, nullptr, bufa,
                                               M, 2 * STATE, HIDDEN, nullptr, nullptr);

        // diagonal complex recurrence -> bufb  (M x 2S)
        scan_kernel<<<(BATCH * STATE) / 128, 128>>>(bufa, bufb);

        // y = gelu( [h_re|h_im] @ [C_re|-C_im]^T + h*D ) -> bufa  (M x H)
        sgemm_kernel<128, 8, 1><<<g512, blk>>>(bufb, Wc, nullptr, bufa,
                                               M, HIDDEN, 2 * STATE, bufh, Dv + l * HIDDEN);

        // u = y @ W1^T + b1 -> bufb
        sgemm_kernel<128, 8, 0><<<g512, blk>>>(bufa, W1 + (size_t)l * HIDDEN * HIDDEN,
                                               b1 + l * HIDDEN, bufb,
                                               M, HIDDEN, HIDDEN, nullptr, nullptr);

        // h = u * sigmoid(y @ W2^T + b2) + h   (in-place on bufh)
        sgemm_kernel<128, 8, 2><<<g512, blk>>>(bufa, W2 + (size_t)l * HIDDEN * HIDDEN,
                                               b2 + l * HIDDEN, bufh,
                                               M, HIDDEN, HIDDEN, bufb, bufh);
    }

    // out = h @ outW^T + outb
    sgemm_kernel<64, 4, 0><<<gout, blk>>>(bufh, outW, outb, out, M, DOUT, HIDDEN,
                                          nullptr, nullptr);
}

// round 5
// speedup vs baseline: 4.1525x; 4.1525x over previous
#include <cuda_runtime.h>
#include <cstdint>
#include <math.h>

#define BATCH   16
#define SEQ     2048
#define DIN     128
#define HIDDEN  512
#define STATE   256
#define DOUT    64
#define NLAYERS 4
#define MROWS   (BATCH * SEQ)   /* 32768 */
#define NCH     16
#define CLEN    (SEQ / NCH)     /* 128 */

// ---------------- scratch (allocation-free: __device__ globals) ----------------
__device__ float  g_bufh[(size_t)MROWS * HIDDEN];   // residual stream h
__device__ float  g_bufa[(size_t)MROWS * HIDDEN];   // Bu / y
__device__ float  g_bufb[(size_t)MROWS * HIDDEN];   // scan out / u
__device__ float  g_Bn [2 * STATE * HIDDEN];        // rows interleaved: 2s=re,2s+1=im
__device__ float  g_Wc [HIDDEN * 2 * STATE];        // cols interleaved: 2s=Cre,2s+1=-Cim
__device__ float2 g_lam2[STATE];
__device__ float2 g_carry[BATCH * NCH * STATE];
__device__ float2 g_cin  [BATCH * NCH * STATE];

// ---------------- per-layer small precompute ----------------
__global__ void prep_kernel(const float* __restrict__ nu, const float* __restrict__ th,
                            const float* __restrict__ ga,
                            const float* __restrict__ Bre, const float* __restrict__ Bim,
                            const float* __restrict__ Cre, const float* __restrict__ Cim)
{
    int tid = blockIdx.x * blockDim.x + threadIdx.x;
    int stride = gridDim.x * blockDim.x;
    if (tid < STATE) {
        float mag = expf(-expf(nu[tid]));
        float ang = expf(th[tid]);
        g_lam2[tid] = make_float2(mag * cosf(ang), mag * sinf(ang));
    }
    for (int idx = tid; idx < STATE * HIDDEN; idx += stride) {
        int s = idx / HIDDEN, h = idx % HIDDEN;
        float g = expf(ga[s]);
        g_Bn[(size_t)(2 * s)     * HIDDEN + h] = Bre[idx] * g;
        g_Bn[(size_t)(2 * s + 1) * HIDDEN + h] = Bim[idx] * g;
    }
    for (int idx = tid; idx < HIDDEN * STATE; idx += stride) {
        int h = idx / STATE, s = idx % STATE;
        g_Wc[(size_t)h * (2 * STATE) + 2 * s]     =  Cre[idx];
        g_Wc[(size_t)h * (2 * STATE) + 2 * s + 1] = -Cim[idx];
    }
}

// ---------------- chunked diagonal complex scan ----------------
// Bu layout (interleaved): row m, float2 col s = (re, im)
__global__ void scanA_kernel(const float* __restrict__ Bu)
{
    int t = blockIdx.x * blockDim.x + threadIdx.x;   // 65536
    int s  = t & (STATE - 1);
    int ch = (t >> 8) & (NCH - 1);
    int b  = t >> 12;
    float2 l = g_lam2[s];
    const float2* src = (const float2*)Bu + ((size_t)(b * SEQ + ch * CLEN)) * STATE + s;
    float hr = 0.f, hi = 0.f;
#pragma unroll 4
    for (int i = 0; i < CLEN; i++) {
        float2 u = src[(size_t)i * STATE];
        float nr = fmaf(l.x, hr, fmaf(-l.y, hi, u.x));
        float ni = fmaf(l.x, hi, fmaf( l.y, hr, u.y));
        hr = nr; hi = ni;
    }
    g_carry[(b * NCH + ch) * STATE + s] = make_float2(hr, hi);
}

__global__ void scanB_kernel()
{
    int t = blockIdx.x * blockDim.x + threadIdx.x;   // 4096
    int s = t & (STATE - 1);
    int b = t >> 8;
    float2 l = g_lam2[s];
    float pr = l.x, pi = l.y;
#pragma unroll
    for (int k = 0; k < 7; k++) {                    // lam^128
        float nr = pr * pr - pi * pi;
        float ni = 2.f * pr * pi;
        pr = nr; pi = ni;
    }
    float hr = 0.f, hi = 0.f;
#pragma unroll
    for (int ch = 0; ch < NCH; ch++) {
        g_cin[(b * NCH + ch) * STATE + s] = make_float2(hr, hi);
        float2 c = g_carry[(b * NCH + ch) * STATE + s];
        float nr = pr * hr - pi * hi + c.x;
        float ni = pr * hi + pi * hr + c.y;
        hr = nr; hi = ni;
    }
}

__global__ void scanC_kernel(const float* __restrict__ Bu, float* __restrict__ Hs)
{
    int t = blockIdx.x * blockDim.x + threadIdx.x;
    int s  = t & (STATE - 1);
    int ch = (t >> 8) & (NCH - 1);
    int b  = t >> 12;
    float2 l = g_lam2[s];
    size_t base = ((size_t)(b * SEQ + ch * CLEN)) * STATE + s;
    const float2* src = (const float2*)Bu + base;
    float2* dst = (float2*)Hs + base;
    float2 h0 = g_cin[(b * NCH + ch) * STATE + s];
    float hr = h0.x, hi = h0.y;
#pragma unroll 4
    for (int i = 0; i < CLEN; i++) {
        float2 u = src[(size_t)i * STATE];
        float nr = fmaf(l.x, hr, fmaf(-l.y, hi, u.x));
        float ni = fmaf(l.x, hi, fmaf( l.y, hr, u.y));
        hr = nr; hi = ni;
        dst[(size_t)i * STATE] = make_float2(hr, hi);
    }
}

// ---------------- tf32 helpers ----------------
__device__ __forceinline__ uint32_t f2tf(float f) {
    uint32_t u;
    asm("cvt.rna.tf32.f32 %0, %1;" : "=r"(u) : "f"(f));
    return u;
}
__device__ __forceinline__ void mma_tf32(float* d, const uint32_t* a, const uint32_t* b) {
    asm volatile(
        "mma.sync.aligned.m16n8k8.row.col.f32.tf32.tf32.f32 "
        "{%0,%1,%2,%3}, {%4,%5,%6,%7}, {%8,%9}, {%0,%1,%2,%3};"
        : "+f"(d[0]), "+f"(d[1]), "+f"(d[2]), "+f"(d[3])
        : "r"(a[0]), "r"(a[1]), "r"(a[2]), "r"(a[3]), "r"(b[0]), "r"(b[1]));
}

// ---------------- tensor GEMM: C[M,N] = A[M,K] @ W[N,K]^T (+ epilogue) ----------------
// EPI 0: C = acc (+bias[col])
// EPI 1: v = acc + e1[o]*e2[col]; C = gelu_exact(v)
// EPI 2: v = acc + bias[col];     C = e1[o]*sigmoid(v) + e2[o]
template <int BN, int WN, int EPI>
__global__ void __launch_bounds__(256)
mma_gemm(const float* __restrict__ A, const float* __restrict__ W,
         const float* __restrict__ bias, float* __restrict__ C,
         int M, int N, int K,
         const float* __restrict__ e1, const float* __restrict__ e2)
{
    constexpr int BM = 128, BK = 16;
    constexpr int ASTR = BM + 4, BSTR = BN + 4;
    constexpr int AF4 = BM * BK / (4 * 256);          // 2
    constexpr int BF4 = BN * BK / (4 * 256);          // 2 (BN=128) or 1 (BN=64)
    constexpr int NFR = WN / 8;

    __shared__ uint32_t As[2][BK][ASTR];
    __shared__ uint32_t Bs[2][BK][BSTR];

    const int tid = threadIdx.x;
    const int wid = tid >> 5, lane = tid & 31;
    const int g = lane >> 2, tig = lane & 3;
    const int warp_m = wid & 3, warp_n = wid >> 2;    // 4 x 2 warp grid
    const int bm = blockIdx.y * BM;
    const int bn = blockIdx.x * BN;

    float acc[2][NFR][4];
#pragma unroll
    for (int mi = 0; mi < 2; mi++)
#pragma unroll
        for (int ni = 0; ni < NFR; ni++)
#pragma unroll
            for (int j = 0; j < 4; j++) acc[mi][ni][j] = 0.f;

    float4 pa[AF4], pb[BF4];

    auto ldA = [&](int kb) {
#pragma unroll
        for (int i = 0; i < AF4; i++) {
            int id = tid + i * 256;
            int row = id >> 2, kg = id & 3;
            pa[i] = *(const float4*)(A + (size_t)(bm + row) * K + kb * BK + kg * 4);
        }
    };
    auto ldB = [&](int kb) {
#pragma unroll
        for (int i = 0; i < BF4; i++) {
            int id = tid + i * 256;
            int row = id >> 2, kg = id & 3;
            pb[i] = *(const float4*)(W + (size_t)(bn + row) * K + kb * BK + kg * 4);
        }
    };
    auto stA = [&](int buf) {
#pragma unroll
        for (int i = 0; i < AF4; i++) {
            int id = tid + i * 256;
            int row = id >> 2, kg = id & 3;
            As[buf][kg * 4 + 0][row] = f2tf(pa[i].x);
            As[buf][kg * 4 + 1][row] = f2tf(pa[i].y);
            As[buf][kg * 4 + 2][row] = f2tf(pa[i].z);
            As[buf][kg * 4 + 3][row] = f2tf(pa[i].w);
        }
    };
    auto stB = [&](int buf) {
#pragma unroll
        for (int i = 0; i < BF4; i++) {
            int id = tid + i * 256;
            int row = id >> 2, kg = id & 3;
            Bs[buf][kg * 4 + 0][row] = f2tf(pb[i].x);
            Bs[buf][kg * 4 + 1][row] = f2tf(pb[i].y);
            Bs[buf][kg * 4 + 2][row] = f2tf(pb[i].z);
            Bs[buf][kg * 4 + 3][row] = f2tf(pb[i].w);
        }
    };

    const int nkb = K / BK;
    ldA(0); ldB(0);
    stA(0); stB(0);
    __syncthreads();

    for (int kb = 0; kb < nkb; kb++) {
        const int buf = kb & 1;
        if (kb + 1 < nkb) { ldA(kb + 1); ldB(kb + 1); }

#pragma unroll
        for (int ks = 0; ks < 2; ks++) {
            uint32_t afr[2][4];
            uint32_t bfr[NFR][2];
            const int kr = ks * 8;
#pragma unroll
            for (int mi = 0; mi < 2; mi++) {
                int r = warp_m * 32 + mi * 16 + g;
                afr[mi][0] = As[buf][kr + tig][r];
                afr[mi][1] = As[buf][kr + tig][r + 8];
                afr[mi][2] = As[buf][kr + tig + 4][r];
                afr[mi][3] = As[buf][kr + tig + 4][r + 8];
            }
#pragma unroll
            for (int ni = 0; ni < NFR; ni++) {
                int c = warp_n * WN + ni * 8 + g;
                bfr[ni][0] = Bs[buf][kr + tig][c];
                bfr[ni][1] = Bs[buf][kr + tig + 4][c];
            }
#pragma unroll
            for (int mi = 0; mi < 2; mi++)
#pragma unroll
                for (int ni = 0; ni < NFR; ni++)
                    mma_tf32(acc[mi][ni], afr[mi], bfr[ni]);
        }

        if (kb + 1 < nkb) { stA(buf ^ 1); stB(buf ^ 1); }
        __syncthreads();
    }

    // -------- epilogue --------
#pragma unroll
    for (int mi = 0; mi < 2; mi++) {
        int row0 = bm + warp_m * 32 + mi * 16 + g;
        int row1 = row0 + 8;
#pragma unroll
        for (int ni = 0; ni < NFR; ni++) {
            int col = bn + warp_n * WN + ni * 8 + tig * 2;
            size_t o0 = (size_t)row0 * N + col;
            size_t o1 = (size_t)row1 * N + col;
            float r0 = acc[mi][ni][0], r1 = acc[mi][ni][1];
            float r2 = acc[mi][ni][2], r3 = acc[mi][ni][3];
            float2 v0, v1;
            if (EPI == 0) {
                float b0 = bias ? bias[col] : 0.f;
                float b1 = bias ? bias[col + 1] : 0.f;
                v0 = make_float2(r0 + b0, r1 + b1);
                v1 = make_float2(r2 + b0, r3 + b1);
            } else if (EPI == 1) {
                float d0 = e2[col], d1 = e2[col + 1];
                float t0 = r0 + e1[o0] * d0;
                float t1 = r1 + e1[o0 + 1] * d1;
                float t2 = r2 + e1[o1] * d0;
                float t3 = r3 + e1[o1 + 1] * d1;
                v0 = make_float2(t0 * normcdff(t0), t1 * normcdff(t1));
                v1 = make_float2(t2 * normcdff(t2), t3 * normcdff(t3));
            } else {
                float b0 = bias[col], b1 = bias[col + 1];
                float s0 = 1.f / (1.f + expf(-(r0 + b0)));
                float s1 = 1.f / (1.f + expf(-(r1 + b1)));
                float s2 = 1.f / (1.f + expf(-(r2 + b0)));
                float s3 = 1.f / (1.f + expf(-(r3 + b1)));
                v0 = make_float2(fmaf(e1[o0], s0, e2[o0]), fmaf(e1[o0 + 1], s1, e2[o0 + 1]));
                v1 = make_float2(fmaf(e1[o1], s2, e2[o1]), fmaf(e1[o1 + 1], s3, e2[o1 + 1]));
            }
            *(float2*)(C + o0) = v0;
            *(float2*)(C + o1) = v1;
        }
    }
}

// ---------------- launcher ----------------
extern "C" void kernel_launch(void* const* d_in, const int* in_sizes, int n_in,
                              void* d_out, int out_size)
{
    const float* x    = (const float*)d_in[0];
    const float* embW = (const float*)d_in[1];
    const float* embb = (const float*)d_in[2];
    const float* nu   = (const float*)d_in[3];
    const float* th   = (const float*)d_in[4];
    const float* ga   = (const float*)d_in[5];
    const float* Bre  = (const float*)d_in[6];
    const float* Bim  = (const float*)d_in[7];
    const float* Cre  = (const float*)d_in[8];
    const float* Cim  = (const float*)d_in[9];
    const float* Dv   = (const float*)d_in[10];
    const float* W1   = (const float*)d_in[11];
    const float* b1   = (const float*)d_in[12];
    const float* W2   = (const float*)d_in[13];
    const float* b2   = (const float*)d_in[14];
    const float* outW = (const float*)d_in[15];
    const float* outb = (const float*)d_in[16];
    float* out = (float*)d_out;
    (void)in_sizes; (void)n_in; (void)out_size;

    float *bufh, *bufa, *bufb, *Bn, *Wc;
    cudaGetSymbolAddress((void**)&bufh, g_bufh);
    cudaGetSymbolAddress((void**)&bufa, g_bufa);
    cudaGetSymbolAddress((void**)&bufb, g_bufb);
    cudaGetSymbolAddress((void**)&Bn,  g_Bn);
    cudaGetSymbolAddress((void**)&Wc,  g_Wc);

    const int M = MROWS;
    dim3 blk(256);
    dim3 g512(HIDDEN / 128, M / 128);     // (4, 256)
    dim3 gout(1, M / 128);

    // embedding: h = x @ embW^T + embb
    mma_gemm<128, 64, 0><<<g512, blk>>>(x, embW, embb, bufh, M, HIDDEN, DIN,
                                        nullptr, nullptr);

    for (int l = 0; l < NLAYERS; l++) {
        prep_kernel<<<128, 256>>>(nu + l * STATE, th + l * STATE, ga + l * STATE,
                                  Bre + (size_t)l * STATE * HIDDEN,
                                  Bim + (size_t)l * STATE * HIDDEN,
                                  Cre + (size_t)l * HIDDEN * STATE,
                                  Cim + (size_t)l * HIDDEN * STATE);

        // Bu = h @ Bn^T -> bufa  (M x 2S, re/im interleaved)
        mma_gemm<128, 64, 0><<<g512, blk>>>(bufh, Bn, nullptr, bufa,
                                            M, 2 * STATE, HIDDEN, nullptr, nullptr);

        // chunked diagonal complex scan: bufa -> bufb
        scanA_kernel<<<256, 256>>>(bufa);
        scanB_kernel<<<16, 256>>>();
        scanC_kernel<<<256, 256>>>(bufa, bufb);

        // y = gelu( Hs @ Wc^T + h*D ) -> bufa
        mma_gemm<128, 64, 1><<<g512, blk>>>(bufb, Wc, nullptr, bufa,
                                            M, HIDDEN, 2 * STATE, bufh, Dv + l * HIDDEN);

        // u = y @ W1^T + b1 -> bufb
        mma_gemm<128, 64, 0><<<g512, blk>>>(bufa, W1 + (size_t)l * HIDDEN * HIDDEN,
                                            b1 + l * HIDDEN, bufb,
                                            M, HIDDEN, HIDDEN, nullptr, nullptr);

        // h = u * sigmoid(y @ W2^T + b2) + h   (in-place on bufh)
        mma_gemm<128, 64, 2><<<g512, blk>>>(bufa, W2 + (size_t)l * HIDDEN * HIDDEN,
                                            b2 + l * HIDDEN, bufh,
                                            M, HIDDEN, HIDDEN, bufb, bufh);
    }

    // out = h @ outW^T + outb
    mma_gemm<64, 32, 0><<<gout, blk>>>(bufh, outW, outb, out, M, DOUT, HIDDEN,
                                       nullptr, nullptr);
}

// round 7
// speedup vs baseline: 5.8680x; 1.4131x over previous
#include <cuda_runtime.h>
#include <cstdint>
#include <math.h>

#define BATCH   16
#define SEQ     2048
#define DIN     128
#define HIDDEN  512
#define STATE   256
#define DOUT    64
#define NLAYERS 4
#define MROWS   (BATCH * SEQ)   /* 32768 */
#define NCH     64
#define CLEN    (SEQ / NCH)     /* 32 */

// ---------------- scratch (allocation-free: __device__ globals) ----------------
__device__ float  g_bufh[(size_t)MROWS * HIDDEN];   // residual stream h
__device__ float  g_bufa[(size_t)MROWS * HIDDEN];   // Bu / y
__device__ float  g_bufb[(size_t)MROWS * HIDDEN];   // scan out Hs
__device__ float  g_Bn [2 * STATE * HIDDEN];        // rows interleaved 2s/2s+1, tf32-rounded
__device__ float  g_Wc [HIDDEN * 2 * STATE];        // cols interleaved, tf32-rounded
__device__ float  g_W1t[HIDDEN * HIDDEN];           // tf32-rounded W1 (per layer)
__device__ float  g_W2t[HIDDEN * HIDDEN];           // tf32-rounded W2 (per layer)
__device__ float  g_embWt[HIDDEN * DIN];
__device__ float  g_outWt[DOUT * HIDDEN];
__device__ float2 g_lam2[STATE];
__device__ float2 g_carry[BATCH * NCH * STATE];
__device__ float2 g_cin  [BATCH * NCH * STATE];

// ---------------- tf32 helpers ----------------
__device__ __forceinline__ uint32_t f2tf(float f) {
    uint32_t u;
    asm("cvt.rna.tf32.f32 %0, %1;" : "=r"(u) : "f"(f));
    return u;
}
__device__ __forceinline__ float tfround(float f) { return __uint_as_float(f2tf(f)); }

__device__ __forceinline__ void mma_tf32(float* d, const uint32_t* a, const uint32_t* b) {
    asm volatile(
        "mma.sync.aligned.m16n8k8.row.col.f32.tf32.tf32.f32 "
        "{%0,%1,%2,%3}, {%4,%5,%6,%7}, {%8,%9}, {%0,%1,%2,%3};"
        : "+f"(d[0]), "+f"(d[1]), "+f"(d[2]), "+f"(d[3])
        : "r"(a[0]), "r"(a[1]), "r"(a[2]), "r"(a[3]), "r"(b[0]), "r"(b[1]));
}
__device__ __forceinline__ void cp16(void* s, const void* g) {
    uint32_t sa = (uint32_t)__cvta_generic_to_shared(s);
    asm volatile("cp.async.cg.shared.global [%0], [%1], 16;" :: "r"(sa), "l"(g));
}
#define CP_COMMIT() asm volatile("cp.async.commit_group;" ::: "memory")
#define CP_WAIT(n)  asm volatile("cp.async.wait_group %0;" :: "n"(n) : "memory")

// ---------------- one-time weight rounding ----------------
__global__ void prep0_kernel(const float* __restrict__ embW, const float* __restrict__ outW)
{
    int tid = blockIdx.x * blockDim.x + threadIdx.x;
    int stride = gridDim.x * blockDim.x;
    for (int i = tid; i < HIDDEN * DIN; i += stride) g_embWt[i] = tfround(embW[i]);
    for (int i = tid; i < DOUT * HIDDEN; i += stride) g_outWt[i] = tfround(outW[i]);
}

// ---------------- per-layer small precompute ----------------
__global__ void prep_kernel(const float* __restrict__ nu, const float* __restrict__ th,
                            const float* __restrict__ ga,
                            const float* __restrict__ Bre, const float* __restrict__ Bim,
                            const float* __restrict__ Cre, const float* __restrict__ Cim,
                            const float* __restrict__ W1, const float* __restrict__ W2)
{
    int tid = blockIdx.x * blockDim.x + threadIdx.x;
    int stride = gridDim.x * blockDim.x;
    if (tid < STATE) {
        float mag = expf(-expf(nu[tid]));
        float ang = expf(th[tid]);
        g_lam2[tid] = make_float2(mag * cosf(ang), mag * sinf(ang));
    }
    for (int idx = tid; idx < STATE * HIDDEN; idx += stride) {
        int s = idx / HIDDEN, h = idx % HIDDEN;
        float g = expf(ga[s]);
        g_Bn[(size_t)(2 * s)     * HIDDEN + h] = tfround(Bre[idx] * g);
        g_Bn[(size_t)(2 * s + 1) * HIDDEN + h] = tfround(Bim[idx] * g);
    }
    for (int idx = tid; idx < HIDDEN * STATE; idx += stride) {
        int h = idx / STATE, s = idx % STATE;
        g_Wc[(size_t)h * (2 * STATE) + 2 * s]     = tfround( Cre[idx]);
        g_Wc[(size_t)h * (2 * STATE) + 2 * s + 1] = tfround(-Cim[idx]);
    }
    for (int idx = tid; idx < HIDDEN * HIDDEN; idx += stride) {
        g_W1t[idx] = tfround(W1[idx]);
        g_W2t[idx] = tfround(W2[idx]);
    }
}

// ---------------- chunked diagonal complex scan (NCH=64, CLEN=32) ----------------
// Bu layout (interleaved): row m, float2 col s = (re, im)
__global__ void scanA_kernel(const float* __restrict__ Bu)
{
    int t = blockIdx.x * blockDim.x + threadIdx.x;   // 262144
    int s  = t & (STATE - 1);
    int ch = (t >> 8) & (NCH - 1);
    int b  = t >> 14;
    float2 l = g_lam2[s];
    const float2* src = (const float2*)Bu + ((size_t)(b * SEQ + ch * CLEN)) * STATE + s;
    float hr = 0.f, hi = 0.f;
#pragma unroll 4
    for (int i = 0; i < CLEN; i++) {
        float2 u = src[(size_t)i * STATE];
        float nr = fmaf(l.x, hr, fmaf(-l.y, hi, u.x));
        float ni = fmaf(l.x, hi, fmaf( l.y, hr, u.y));
        hr = nr; hi = ni;
    }
    g_carry[(b * NCH + ch) * STATE + s] = make_float2(hr, hi);
}

__global__ void scanB_kernel()
{
    int t = blockIdx.x * blockDim.x + threadIdx.x;   // 4096
    int s = t & (STATE - 1);
    int b = t >> 8;
    float2 l = g_lam2[s];
    float pr = l.x, pi = l.y;
#pragma unroll
    for (int k = 0; k < 5; k++) {                    // lam^32
        float nr = pr * pr - pi * pi;
        float ni = 2.f * pr * pi;
        pr = nr; pi = ni;
    }
    float hr = 0.f, hi = 0.f;
#pragma unroll
    for (int ch = 0; ch < NCH; ch++) {
        g_cin[(b * NCH + ch) * STATE + s] = make_float2(hr, hi);
        float2 c = g_carry[(b * NCH + ch) * STATE + s];
        float nr = pr * hr - pi * hi + c.x;
        float ni = pr * hi + pi * hr + c.y;
        hr = nr; hi = ni;
    }
}

__global__ void scanC_kernel(const float* __restrict__ Bu, float* __restrict__ Hs)
{
    int t = blockIdx.x * blockDim.x + threadIdx.x;
    int s  = t & (STATE - 1);
    int ch = (t >> 8) & (NCH - 1);
    int b  = t >> 14;
    float2 l = g_lam2[s];
    size_t base = ((size_t)(b * SEQ + ch * CLEN)) * STATE + s;
    const float2* src = (const float2*)Bu + base;
    float2* dst = (float2*)Hs + base;
    float2 h0 = g_cin[(b * NCH + ch) * STATE + s];
    float hr = h0.x, hi = h0.y;
#pragma unroll 4
    for (int i = 0; i < CLEN; i++) {
        float2 u = src[(size_t)i * STATE];
        float nr = fmaf(l.x, hr, fmaf(-l.y, hi, u.x));
        float ni = fmaf(l.x, hi, fmaf( l.y, hr, u.y));
        hr = nr; hi = ni;
        dst[(size_t)i * STATE] = make_float2(tfround(hr), tfround(hi));  // feeds GEMM A only
    }
}

// ---------------- pipelined tf32 MMA GEMM: C[M,N] = A[M,K] @ W[N,K]^T ----------------
// EPI 0: C = acc (+bias[col])                                   (no rounding)
// EPI 1: v = acc + e1[o]*e2[col]; C = tfround(gelu_exact(v))    (y, feeds GEMMs only)
// DUAL : u = acc+bias, g = acc2+bias2; C = u*sigmoid(g) + e1[o] (GLU + residual)
template <int BN, int EPI, bool CVTA, bool DUAL>
__global__ void __launch_bounds__(256, 2)
mma_gemm(const float* __restrict__ A, const float* __restrict__ W,
         const float* __restrict__ W2p,
         const float* __restrict__ bias, const float* __restrict__ bias2,
         float* __restrict__ C, int M, int N, int K,
         const float* __restrict__ e1, const float* __restrict__ e2)
{
    constexpr int BM = 128, BK = 16, RS = BK + 4;     // row stride (floats)
    constexpr int STAGES = 4;
    constexpr int WN = BN / 2, NFR = WN / 8;
    constexpr int NBTILE = DUAL ? 2 * BN : BN;
    constexpr int STAGE_F = (BM + NBTILE) * RS;
    constexpr int ACH = BM * BK / 4 / 256;            // 2
    constexpr int BCH = BN * BK / 4 / 256;            // 2 (BN=128) / 1 (BN=64)

    extern __shared__ float smem[];

    const int tid = threadIdx.x;
    const int wid = tid >> 5, lane = tid & 31;
    const int g = lane >> 2, tig = lane & 3;
    const int warp_m = wid & 3, warp_n = wid >> 2;    // 4 x 2
    const int bm = blockIdx.y * BM;
    const int bn = blockIdx.x * BN;

    float acc[2][NFR][4];
    float acc2[DUAL ? 2 : 1][DUAL ? NFR : 1][4];
#pragma unroll
    for (int mi = 0; mi < 2; mi++)
#pragma unroll
        for (int ni = 0; ni < NFR; ni++)
#pragma unroll
            for (int j = 0; j < 4; j++) {
                acc[mi][ni][j] = 0.f;
                if (DUAL) acc2[mi][ni][j] = 0.f;
            }

    const int nkb = K / BK;

    auto issue = [&](int kb) {
        float* Sb = smem + (kb % STAGES) * STAGE_F;
        const float* Ag = A + (size_t)bm * K + kb * BK;
#pragma unroll
        for (int i = 0; i < ACH; i++) {
            int c = tid + i * 256;
            int r = c >> 2, kc = c & 3;
            cp16(Sb + r * RS + kc * 4, Ag + (size_t)r * K + kc * 4);
        }
        const float* Wg = W + (size_t)bn * K + kb * BK;
        float* Bb = Sb + BM * RS;
#pragma unroll
        for (int i = 0; i < BCH; i++) {
            int c = tid + i * 256;
            int r = c >> 2, kc = c & 3;
            cp16(Bb + r * RS + kc * 4, Wg + (size_t)r * K + kc * 4);
        }
        if (DUAL) {
            const float* W2g = W2p + (size_t)bn * K + kb * BK;
            float* B2b = Sb + (BM + BN) * RS;
#pragma unroll
            for (int i = 0; i < BCH; i++) {
                int c = tid + i * 256;
                int r = c >> 2, kc = c & 3;
                cp16(B2b + r * RS + kc * 4, W2g + (size_t)r * K + kc * 4);
            }
        }
    };

#pragma unroll
    for (int s = 0; s < STAGES - 1; s++) { issue(s); CP_COMMIT(); }

    for (int kb = 0; kb < nkb; kb++) {
        CP_WAIT(STAGES - 2);
        __syncthreads();
        if (kb + STAGES - 1 < nkb) issue(kb + STAGES - 1);
        CP_COMMIT();

        const float* As_  = smem + (kb % STAGES) * STAGE_F;
        const float* Bs_  = As_ + BM * RS;
        const float* B2s_ = As_ + (BM + BN) * RS;

#pragma unroll
        for (int ks = 0; ks < 2; ks++) {
            const int kr = ks * 8;
            uint32_t afr[2][4];
#pragma unroll
            for (int mi = 0; mi < 2; mi++) {
                int r = warp_m * 32 + mi * 16 + g;
                float v0 = As_[(size_t)r * RS + kr + tig];
                float v1 = As_[(size_t)(r + 8) * RS + kr + tig];
                float v2 = As_[(size_t)r * RS + kr + tig + 4];
                float v3 = As_[(size_t)(r + 8) * RS + kr + tig + 4];
                if (CVTA) {
                    afr[mi][0] = f2tf(v0); afr[mi][1] = f2tf(v1);
                    afr[mi][2] = f2tf(v2); afr[mi][3] = f2tf(v3);
                } else {
                    afr[mi][0] = __float_as_uint(v0); afr[mi][1] = __float_as_uint(v1);
                    afr[mi][2] = __float_as_uint(v2); afr[mi][3] = __float_as_uint(v3);
                }
            }
            uint32_t bfr[NFR][2], bfr2[NFR][2];
#pragma unroll
            for (int ni = 0; ni < NFR; ni++) {
                int c = warp_n * WN + ni * 8 + g;
                bfr[ni][0] = __float_as_uint(Bs_[(size_t)c * RS + kr + tig]);
                bfr[ni][1] = __float_as_uint(Bs_[(size_t)c * RS + kr + tig + 4]);
                if (DUAL) {
                    bfr2[ni][0] = __float_as_uint(B2s_[(size_t)c * RS + kr + tig]);
                    bfr2[ni][1] = __float_as_uint(B2s_[(size_t)c * RS + kr + tig + 4]);
                }
            }
#pragma unroll
            for (int mi = 0; mi < 2; mi++)
#pragma unroll
                for (int ni = 0; ni < NFR; ni++) {
                    mma_tf32(acc[mi][ni], afr[mi], bfr[ni]);
                    if (DUAL) mma_tf32(acc2[mi][ni], afr[mi], bfr2[ni]);
                }
        }
        __syncthreads();
    }

    // -------- epilogue --------
#pragma unroll
    for (int mi = 0; mi < 2; mi++) {
        int row0 = bm + warp_m * 32 + mi * 16 + g;
        int row1 = row0 + 8;
#pragma unroll
        for (int ni = 0; ni < NFR; ni++) {
            int col = bn + warp_n * WN + ni * 8 + tig * 2;
            size_t o0 = (size_t)row0 * N + col;
            size_t o1 = (size_t)row1 * N + col;
            float r0 = acc[mi][ni][0], r1 = acc[mi][ni][1];
            float r2 = acc[mi][ni][2], r3 = acc[mi][ni][3];
            float2 v0, v1;
            if (DUAL) {
                float b10 = bias[col], b11 = bias[col + 1];
                float b20 = bias2[col], b21 = bias2[col + 1];
                float q0 = acc2[mi][ni][0], q1 = acc2[mi][ni][1];
                float q2 = acc2[mi][ni][2], q3 = acc2[mi][ni][3];
                float s0 = 1.f / (1.f + expf(-(q0 + b20)));
                float s1 = 1.f / (1.f + expf(-(q1 + b21)));
                float s2 = 1.f / (1.f + expf(-(q2 + b20)));
                float s3 = 1.f / (1.f + expf(-(q3 + b21)));
                v0 = make_float2(fmaf(r0 + b10, s0, e1[o0]), fmaf(r1 + b11, s1, e1[o0 + 1]));
                v1 = make_float2(fmaf(r2 + b10, s2, e1[o1]), fmaf(r3 + b11, s3, e1[o1 + 1]));
            } else if (EPI == 0) {
                float b0 = bias ? bias[col] : 0.f;
                float b1 = bias ? bias[col + 1] : 0.f;
                v0 = make_float2(r0 + b0, r1 + b1);
                v1 = make_float2(r2 + b0, r3 + b1);
            } else {
                float d0 = e2[col], d1 = e2[col + 1];
                float t0 = r0 + e1[o0] * d0;
                float t1 = r1 + e1[o0 + 1] * d1;
                float t2 = r2 + e1[o1] * d0;
                float t3 = r3 + e1[o1 + 1] * d1;
                v0 = make_float2(tfround(t0 * normcdff(t0)), tfround(t1 * normcdff(t1)));
                v1 = make_float2(tfround(t2 * normcdff(t2)), tfround(t3 * normcdff(t3)));
            }
            *(float2*)(C + o0) = v0;
            *(float2*)(C + o1) = v1;
        }
    }
}

// ---------------- launcher ----------------
extern "C" void kernel_launch(void* const* d_in, const int* in_sizes, int n_in,
                              void* d_out, int out_size)
{
    const float* x    = (const float*)d_in[0];
    const float* embW = (const float*)d_in[1];
    const float* embb = (const float*)d_in[2];
    const float* nu   = (const float*)d_in[3];
    const float* th   = (const float*)d_in[4];
    const float* ga   = (const float*)d_in[5];
    const float* Bre  = (const float*)d_in[6];
    const float* Bim  = (const float*)d_in[7];
    const float* Cre  = (const float*)d_in[8];
    const float* Cim  = (const float*)d_in[9];
    const float* Dv   = (const float*)d_in[10];
    const float* W1   = (const float*)d_in[11];
    const float* b1   = (const float*)d_in[12];
    const float* W2   = (const float*)d_in[13];
    const float* b2   = (const float*)d_in[14];
    const float* outW = (const float*)d_in[15];
    const float* outb = (const float*)d_in[16];
    float* out = (float*)d_out;
    (void)in_sizes; (void)n_in; (void)out_size;

    float *bufh, *bufa, *bufb, *Bn, *Wc, *W1t, *W2t, *embWt, *outWt;
    cudaGetSymbolAddress((void**)&bufh, g_bufh);
    cudaGetSymbolAddress((void**)&bufa, g_bufa);
    cudaGetSymbolAddress((void**)&bufb, g_bufb);
    cudaGetSymbolAddress((void**)&Bn,  g_Bn);
    cudaGetSymbolAddress((void**)&Wc,  g_Wc);
    cudaGetSymbolAddress((void**)&W1t, g_W1t);
    cudaGetSymbolAddress((void**)&W2t, g_W2t);
    cudaGetSymbolAddress((void**)&embWt, g_embWt);
    cudaGetSymbolAddress((void**)&outWt, g_outWt);

    // dynamic smem sizes: (BM + NBTILE) * 20 floats * 4 stages * 4B
    const int SM_N128 = (128 + 128) * 20 * 4 * 4;   // 81920
    const int SM_DUAL = (128 + 128) * 20 * 4 * 4;   // 81920
    const int SM_OUT  = (128 + 64) * 20 * 4 * 4;    // 61440
    cudaFuncSetAttribute(mma_gemm<128, 0, true,  false>, cudaFuncAttributeMaxDynamicSharedMemorySize, SM_N128);
    cudaFuncSetAttribute(mma_gemm<128, 1, false, false>, cudaFuncAttributeMaxDynamicSharedMemorySize, SM_N128);
    cudaFuncSetAttribute(mma_gemm<64,  0, false, true >, cudaFuncAttributeMaxDynamicSharedMemorySize, SM_DUAL);
    cudaFuncSetAttribute(mma_gemm<64,  0, true,  false>, cudaFuncAttributeMaxDynamicSharedMemorySize, SM_OUT);

    const int M = MROWS;
    dim3 blk(256);
    dim3 g512(HIDDEN / 128, M / 128);     // (4, 256)
    dim3 gdual(HIDDEN / 64, M / 128);     // (8, 256)
    dim3 gout(1, M / 128);

    prep0_kernel<<<64, 256>>>(embW, outW);

    // embedding: h = x @ embWt^T + embb
    mma_gemm<128, 0, true, false><<<g512, blk, SM_N128>>>(
        x, embWt, nullptr, embb, nullptr, bufh, M, HIDDEN, DIN, nullptr, nullptr);

    for (int l = 0; l < NLAYERS; l++) {
        prep_kernel<<<128, 256>>>(nu + l * STATE, th + l * STATE, ga + l * STATE,
                                  Bre + (size_t)l * STATE * HIDDEN,
                                  Bim + (size_t)l * STATE * HIDDEN,
                                  Cre + (size_t)l * HIDDEN * STATE,
                                  Cim + (size_t)l * HIDDEN * STATE,
                                  W1 + (size_t)l * HIDDEN * HIDDEN,
                                  W2 + (size_t)l * HIDDEN * HIDDEN);

        // Bu = h @ Bn^T -> bufa  (M x 2S, re/im interleaved)
        mma_gemm<128, 0, true, false><<<g512, blk, SM_N128>>>(
            bufh, Bn, nullptr, nullptr, nullptr, bufa, M, 2 * STATE, HIDDEN, nullptr, nullptr);

        // chunked diagonal complex scan: bufa -> bufb (tf32-rounded)
        scanA_kernel<<<1024, 256>>>(bufa);
        scanB_kernel<<<16, 256>>>();
        scanC_kernel<<<1024, 256>>>(bufa, bufb);

        // y = tfround(gelu( Hs @ Wc^T + h*D )) -> bufa
        mma_gemm<128, 1, false, false><<<g512, blk, SM_N128>>>(
            bufb, Wc, nullptr, nullptr, nullptr, bufa, M, HIDDEN, 2 * STATE, bufh, Dv + l * HIDDEN);

        // h = (y@W1t + b1) * sigmoid(y@W2t + b2) + h   (fused dual GEMM, in-place bufh)
        mma_gemm<64, 0, false, true><<<gdual, blk, SM_DUAL>>>(
            bufa, W1t, W2t, b1 + l * HIDDEN, b2 + l * HIDDEN, bufh,
            M, HIDDEN, HIDDEN, bufh, nullptr);
    }

    // out = h @ outWt^T + outb
    mma_gemm<64, 0, true, false><<<gout, blk, SM_OUT>>>(
        bufh, outWt, nullptr, outb, nullptr, out, M, DOUT, HIDDEN, nullptr, nullptr);
}

// round 8
// speedup vs baseline: 7.1205x; 1.2134x over previous
#include <cuda_runtime.h>
#include <cstdint>
#include <math.h>

#define BATCH   16
#define SEQ     2048
#define DIN     128
#define HIDDEN  512
#define STATE   256
#define DOUT    64
#define NLAYERS 4
#define MROWS   (BATCH * SEQ)   /* 32768 */
#define NCH     64
#define CLEN    (SEQ / NCH)     /* 32 */

// ---------------- scratch (allocation-free: __device__ globals) ----------------
__device__ float  g_bufh[(size_t)MROWS * HIDDEN];   // residual stream h
__device__ float  g_bufa[(size_t)MROWS * HIDDEN];   // Bu / y
__device__ float  g_bufb[(size_t)MROWS * HIDDEN];   // scan out Hs
__device__ float  g_Bn [2 * STATE * HIDDEN];        // rows interleaved 2s/2s+1, tf32-rounded
__device__ float  g_Wc [HIDDEN * 2 * STATE];        // cols interleaved, tf32-rounded
__device__ float  g_W1t[HIDDEN * HIDDEN];           // tf32-rounded W1 (per layer)
__device__ float  g_W2t[HIDDEN * HIDDEN];           // tf32-rounded W2 (per layer)
__device__ float  g_embWt[HIDDEN * DIN];
__device__ float  g_outWt[DOUT * HIDDEN];
__device__ float2 g_lam2[STATE];
__device__ float2 g_carry[BATCH * NCH * STATE];
__device__ float2 g_cin  [BATCH * NCH * STATE];

// ---------------- tf32 / mma helpers ----------------
__device__ __forceinline__ uint32_t f2tf(float f) {
    uint32_t u;
    asm("cvt.rna.tf32.f32 %0, %1;" : "=r"(u) : "f"(f));
    return u;
}
__device__ __forceinline__ float tfround(float f) { return __uint_as_float(f2tf(f)); }

__device__ __forceinline__ void mma_tf32(float* d, const uint32_t* a, const uint32_t* b) {
    asm volatile(
        "mma.sync.aligned.m16n8k8.row.col.f32.tf32.tf32.f32 "
        "{%0,%1,%2,%3}, {%4,%5,%6,%7}, {%8,%9}, {%0,%1,%2,%3};"
        : "+f"(d[0]), "+f"(d[1]), "+f"(d[2]), "+f"(d[3])
        : "r"(a[0]), "r"(a[1]), "r"(a[2]), "r"(a[3]), "r"(b[0]), "r"(b[1]));
}
__device__ __forceinline__ void ldsm4(uint32_t& r0, uint32_t& r1, uint32_t& r2, uint32_t& r3,
                                      uint32_t addr) {
    asm volatile("ldmatrix.sync.aligned.m8n8.x4.shared.b16 {%0,%1,%2,%3}, [%4];"
        : "=r"(r0), "=r"(r1), "=r"(r2), "=r"(r3) : "r"(addr));
}
__device__ __forceinline__ void cp16(void* s, const void* g) {
    uint32_t sa = (uint32_t)__cvta_generic_to_shared(s);
    asm volatile("cp.async.cg.shared.global [%0], [%1], 16;" :: "r"(sa), "l"(g));
}
#define CP_COMMIT() asm volatile("cp.async.commit_group;" ::: "memory")
#define CP_WAIT(n)  asm volatile("cp.async.wait_group %0;" :: "n"(n) : "memory")

// ---------------- one-time weight rounding ----------------
__global__ void prep0_kernel(const float* __restrict__ embW, const float* __restrict__ outW)
{
    int tid = blockIdx.x * blockDim.x + threadIdx.x;
    int stride = gridDim.x * blockDim.x;
    for (int i = tid; i < HIDDEN * DIN; i += stride) g_embWt[i] = tfround(embW[i]);
    for (int i = tid; i < DOUT * HIDDEN; i += stride) g_outWt[i] = tfround(outW[i]);
}

// ---------------- per-layer small precompute ----------------
__global__ void prep_kernel(const float* __restrict__ nu, const float* __restrict__ th,
                            const float* __restrict__ ga,
                            const float* __restrict__ Bre, const float* __restrict__ Bim,
                            const float* __restrict__ Cre, const float* __restrict__ Cim,
                            const float* __restrict__ W1, const float* __restrict__ W2)
{
    int tid = blockIdx.x * blockDim.x + threadIdx.x;
    int stride = gridDim.x * blockDim.x;
    if (tid < STATE) {
        float mag = expf(-expf(nu[tid]));
        float ang = expf(th[tid]);
        g_lam2[tid] = make_float2(mag * cosf(ang), mag * sinf(ang));
    }
    for (int idx = tid; idx < STATE * HIDDEN; idx += stride) {
        int s = idx / HIDDEN, h = idx % HIDDEN;
        float g = expf(ga[s]);
        g_Bn[(size_t)(2 * s)     * HIDDEN + h] = tfround(Bre[idx] * g);
        g_Bn[(size_t)(2 * s + 1) * HIDDEN + h] = tfround(Bim[idx] * g);
    }
    for (int idx = tid; idx < HIDDEN * STATE; idx += stride) {
        int h = idx / STATE, s = idx % STATE;
        g_Wc[(size_t)h * (2 * STATE) + 2 * s]     = tfround( Cre[idx]);
        g_Wc[(size_t)h * (2 * STATE) + 2 * s + 1] = tfround(-Cim[idx]);
    }
    for (int idx = tid; idx < HIDDEN * HIDDEN; idx += stride) {
        g_W1t[idx] = tfround(W1[idx]);
        g_W2t[idx] = tfround(W2[idx]);
    }
}

// ---------------- chunked diagonal complex scan (NCH=64, CLEN=32) ----------------
__global__ void scanA_kernel(const float* __restrict__ Bu)
{
    int t = blockIdx.x * blockDim.x + threadIdx.x;   // 262144
    int s  = t & (STATE - 1);
    int ch = (t >> 8) & (NCH - 1);
    int b  = t >> 14;
    float2 l = g_lam2[s];
    const float2* src = (const float2*)Bu + ((size_t)(b * SEQ + ch * CLEN)) * STATE + s;
    float hr = 0.f, hi = 0.f;
#pragma unroll 4
    for (int i = 0; i < CLEN; i++) {
        float2 u = src[(size_t)i * STATE];
        float nr = fmaf(l.x, hr, fmaf(-l.y, hi, u.x));
        float ni = fmaf(l.x, hi, fmaf( l.y, hr, u.y));
        hr = nr; hi = ni;
    }
    g_carry[(b * NCH + ch) * STATE + s] = make_float2(hr, hi);
}

__global__ void scanB_kernel()
{
    int t = blockIdx.x * blockDim.x + threadIdx.x;   // 4096
    int s = t & (STATE - 1);
    int b = t >> 8;
    float2 l = g_lam2[s];
    float pr = l.x, pi = l.y;
#pragma unroll
    for (int k = 0; k < 5; k++) {                    // lam^32
        float nr = pr * pr - pi * pi;
        float ni = 2.f * pr * pi;
        pr = nr; pi = ni;
    }
    float hr = 0.f, hi = 0.f;
#pragma unroll
    for (int ch = 0; ch < NCH; ch++) {
        g_cin[(b * NCH + ch) * STATE + s] = make_float2(hr, hi);
        float2 c = g_carry[(b * NCH + ch) * STATE + s];
        float nr = pr * hr - pi * hi + c.x;
        float ni = pr * hi + pi * hr + c.y;
        hr = nr; hi = ni;
    }
}

__global__ void scanC_kernel(const float* __restrict__ Bu, float* __restrict__ Hs)
{
    int t = blockIdx.x * blockDim.x + threadIdx.x;
    int s  = t & (STATE - 1);
    int ch = (t >> 8) & (NCH - 1);
    int b  = t >> 14;
    float2 l = g_lam2[s];
    size_t base = ((size_t)(b * SEQ + ch * CLEN)) * STATE + s;
    const float2* src = (const float2*)Bu + base;
    float2* dst = (float2*)Hs + base;
    float2 h0 = g_cin[(b * NCH + ch) * STATE + s];
    float hr = h0.x, hi = h0.y;
#pragma unroll 4
    for (int i = 0; i < CLEN; i++) {
        float2 u = src[(size_t)i * STATE];
        float nr = fmaf(l.x, hr, fmaf(-l.y, hi, u.x));
        float ni = fmaf(l.x, hi, fmaf( l.y, hr, u.y));
        hr = nr; hi = ni;
        dst[(size_t)i * STATE] = make_float2(tfround(hr), tfround(hi));  // feeds GEMM A only
    }
}

// ---------------- pipelined tf32 MMA GEMM (ldmatrix frags): C = A @ W^T ----------------
// EPI 0: C = acc (+bias[col])
// EPI 1: v = acc + e1[o]*e2[col]; C = tfround(gelu_exact(v))
// DUAL : u = acc+bias, g = acc2+bias2; C = u*sigmoid(g) + e1[o]
template <int BN, int EPI, bool CVTA, bool DUAL>
__global__ void __launch_bounds__(256, 2)
mma_gemm(const float* __restrict__ A, const float* __restrict__ W,
         const float* __restrict__ W2p,
         const float* __restrict__ bias, const float* __restrict__ bias2,
         float* __restrict__ C, int M, int N, int K,
         const float* __restrict__ e1, const float* __restrict__ e2)
{
    constexpr int BM = 128, BK = 32, RS = BK + 4;     // row stride = 36 floats (144 B)
    constexpr int STAGES = 3;
    constexpr int WN = BN / 2, NFR = WN / 8, NPAIR = NFR / 2;
    constexpr int NBTILE = DUAL ? 2 * BN : BN;
    constexpr int STAGE_F = (BM + NBTILE) * RS;
    constexpr int STAGE_B = STAGE_F * 4;
    constexpr int BCH = BN / 32;                      // B cp.async chunks per thread

    extern __shared__ float smem[];

    const int tid = threadIdx.x;
    const int wid = tid >> 5, lane = tid & 31;
    const int g = lane >> 2, tig = lane & 3;
    const int warp_m = wid & 3, warp_n = wid >> 2;    // 4 x 2
    const int bm = blockIdx.y * BM;
    const int bn = blockIdx.x * BN;

    // ldmatrix lane addressing: tile t = lane/8, within-row w = lane%8
    const int t8 = lane >> 3, w8 = lane & 7;
    const uint32_t sb0 = (uint32_t)__cvta_generic_to_shared(smem);
    // A: tile t -> rows +8*(t&1), k +4*(t>>1)
    const int arow = warp_m * 32 + (t8 & 1) * 8 + w8;
    uint32_t aoff[2];
    aoff[0] = (uint32_t)((arow * RS + (t8 >> 1) * 4) * 4);
    aoff[1] = aoff[0] + 16 * RS * 4;
    // B: tile t -> col +8*(t>>1), k +4*(t&1)
    uint32_t boff[NPAIR];
#pragma unroll
    for (int p = 0; p < NPAIR; p++) {
        int col = warp_n * WN + p * 16 + (t8 >> 1) * 8 + w8;
        boff[p] = (uint32_t)(((BM + col) * RS + (t8 & 1) * 4) * 4);
    }
    constexpr uint32_t B2OFF = (uint32_t)(BN * RS * 4);

    float acc[2][NFR][4];
    float acc2[DUAL ? 2 : 1][DUAL ? NFR : 1][4];
#pragma unroll
    for (int mi = 0; mi < 2; mi++)
#pragma unroll
        for (int ni = 0; ni < NFR; ni++)
#pragma unroll
            for (int j = 0; j < 4; j++) {
                acc[mi][ni][j] = 0.f;
                if (DUAL) acc2[mi][ni][j] = 0.f;
            }

    const int nkb = K / BK;

    auto issue = [&](int kb, int slot) {
        float* Sb = smem + slot * STAGE_F;
        const float* Ag = A + (size_t)bm * K + kb * BK;
#pragma unroll
        for (int i = 0; i < 4; i++) {
            int c = tid + i * 256;
            int r = c >> 3, kc = c & 7;
            cp16(Sb + r * RS + kc * 4, Ag + (size_t)r * K + kc * 4);
        }
        const float* Wg = W + (size_t)bn * K + kb * BK;
        float* Bb = Sb + BM * RS;
#pragma unroll
        for (int i = 0; i < BCH; i++) {
            int c = tid + i * 256;
            int r = c >> 3, kc = c & 7;
            cp16(Bb + r * RS + kc * 4, Wg + (size_t)r * K + kc * 4);
        }
        if (DUAL) {
            const float* W2g = W2p + (size_t)bn * K + kb * BK;
            float* B2b = Sb + (BM + BN) * RS;
#pragma unroll
            for (int i = 0; i < BCH; i++) {
                int c = tid + i * 256;
                int r = c >> 3, kc = c & 7;
                cp16(B2b + r * RS + kc * 4, W2g + (size_t)r * K + kc * 4);
            }
        }
    };

#pragma unroll
    for (int s = 0; s < STAGES - 1; s++) { issue(s, s); CP_COMMIT(); }

    int rslot = 0, wslot = STAGES - 1;
    for (int kb = 0; kb < nkb; kb++) {
        CP_WAIT(STAGES - 2);
        __syncthreads();
        if (kb + STAGES - 1 < nkb) issue(kb + STAGES - 1, wslot);
        CP_COMMIT();
        if (++wslot == STAGES) wslot = 0;

        const uint32_t sbs = sb0 + rslot * STAGE_B;
#pragma unroll
        for (int ks = 0; ks < 4; ks++) {
            uint32_t afr[2][4];
#pragma unroll
            for (int mi = 0; mi < 2; mi++) {
                ldsm4(afr[mi][0], afr[mi][1], afr[mi][2], afr[mi][3],
                      sbs + aoff[mi] + ks * 32);
                if (CVTA) {
#pragma unroll
                    for (int j = 0; j < 4; j++)
                        afr[mi][j] = f2tf(__uint_as_float(afr[mi][j]));
                }
            }
            uint32_t bfr[NFR][2];
            uint32_t bfr2[DUAL ? NFR : 1][2];
#pragma unroll
            for (int p = 0; p < NPAIR; p++) {
                uint32_t r0, r1, r2, r3;
                ldsm4(r0, r1, r2, r3, sbs + boff[p] + ks * 32);
                bfr[2 * p][0] = r0; bfr[2 * p][1] = r1;
                bfr[2 * p + 1][0] = r2; bfr[2 * p + 1][1] = r3;
                if (DUAL) {
                    ldsm4(r0, r1, r2, r3, sbs + boff[p] + B2OFF + ks * 32);
                    bfr2[2 * p][0] = r0; bfr2[2 * p][1] = r1;
                    bfr2[2 * p + 1][0] = r2; bfr2[2 * p + 1][1] = r3;
                }
            }
#pragma unroll
            for (int mi = 0; mi < 2; mi++)
#pragma unroll
                for (int ni = 0; ni < NFR; ni++) {
                    mma_tf32(acc[mi][ni], afr[mi], bfr[ni]);
                    if (DUAL) mma_tf32(acc2[mi][ni], afr[mi], bfr2[ni]);
                }
        }
        if (++rslot == STAGES) rslot = 0;
    }

    // -------- epilogue --------
#pragma unroll
    for (int mi = 0; mi < 2; mi++) {
        int row0 = bm + warp_m * 32 + mi * 16 + g;
        int row1 = row0 + 8;
#pragma unroll
        for (int ni = 0; ni < NFR; ni++) {
            int col = bn + warp_n * WN + ni * 8 + tig * 2;
            size_t o0 = (size_t)row0 * N + col;
            size_t o1 = (size_t)row1 * N + col;
            float r0 = acc[mi][ni][0], r1 = acc[mi][ni][1];
            float r2 = acc[mi][ni][2], r3 = acc[mi][ni][3];
            float2 v0, v1;
            if (DUAL) {
                float b10 = bias[col], b11 = bias[col + 1];
                float b20 = bias2[col], b21 = bias2[col + 1];
                float q0 = acc2[mi][ni][0], q1 = acc2[mi][ni][1];
                float q2 = acc2[mi][ni][2], q3 = acc2[mi][ni][3];
                float s0 = 1.f / (1.f + expf(-(q0 + b20)));
                float s1 = 1.f / (1.f + expf(-(q1 + b21)));
                float s2 = 1.f / (1.f + expf(-(q2 + b20)));
                float s3 = 1.f / (1.f + expf(-(q3 + b21)));
                v0 = make_float2(fmaf(r0 + b10, s0, e1[o0]), fmaf(r1 + b11, s1, e1[o0 + 1]));
                v1 = make_float2(fmaf(r2 + b10, s2, e1[o1]), fmaf(r3 + b11, s3, e1[o1 + 1]));
            } else if (EPI == 0) {
                float b0 = bias ? bias[col] : 0.f;
                float b1 = bias ? bias[col + 1] : 0.f;
                v0 = make_float2(r0 + b0, r1 + b1);
                v1 = make_float2(r2 + b0, r3 + b1);
            } else {
                float d0 = e2[col], d1 = e2[col + 1];
                float t0 = r0 + e1[o0] * d0;
                float t1 = r1 + e1[o0 + 1] * d1;
                float t2 = r2 + e1[o1] * d0;
                float t3 = r3 + e1[o1 + 1] * d1;
                v0 = make_float2(tfround(t0 * normcdff(t0)), tfround(t1 * normcdff(t1)));
                v1 = make_float2(tfround(t2 * normcdff(t2)), tfround(t3 * normcdff(t3)));
            }
            *(float2*)(C + o0) = v0;
            *(float2*)(C + o1) = v1;
        }
    }
}

// ---------------- launcher ----------------
extern "C" void kernel_launch(void* const* d_in, const int* in_sizes, int n_in,
                              void* d_out, int out_size)
{
    const float* x    = (const float*)d_in[0];
    const float* embW = (const float*)d_in[1];
    const float* embb = (const float*)d_in[2];
    const float* nu   = (const float*)d_in[3];
    const float* th   = (const float*)d_in[4];
    const float* ga   = (const float*)d_in[5];
    const float* Bre  = (const float*)d_in[6];
    const float* Bim  = (const float*)d_in[7];
    const float* Cre  = (const float*)d_in[8];
    const float* Cim  = (const float*)d_in[9];
    const float* Dv   = (const float*)d_in[10];
    const float* W1   = (const float*)d_in[11];
    const float* b1   = (const float*)d_in[12];
    const float* W2   = (const float*)d_in[13];
    const float* b2   = (const float*)d_in[14];
    const float* outW = (const float*)d_in[15];
    const float* outb = (const float*)d_in[16];
    float* out = (float*)d_out;
    (void)in_sizes; (void)n_in; (void)out_size;

    float *bufh, *bufa, *bufb, *Bn, *Wc, *W1t, *W2t, *embWt, *outWt;
    cudaGetSymbolAddress((void**)&bufh, g_bufh);
    cudaGetSymbolAddress((void**)&bufa, g_bufa);
    cudaGetSymbolAddress((void**)&bufb, g_bufb);
    cudaGetSymbolAddress((void**)&Bn,  g_Bn);
    cudaGetSymbolAddress((void**)&Wc,  g_Wc);
    cudaGetSymbolAddress((void**)&W1t, g_W1t);
    cudaGetSymbolAddress((void**)&W2t, g_W2t);
    cudaGetSymbolAddress((void**)&embWt, g_embWt);
    cudaGetSymbolAddress((void**)&outWt, g_outWt);

    // smem: (BM + NBTILE) * 36 floats * 3 stages * 4B
    const int SM_MAIN = (128 + 128) * 36 * 3 * 4;   // 110592
    const int SM_OUT  = (128 + 64) * 36 * 3 * 4;    // 82944
    cudaFuncSetAttribute(mma_gemm<128, 0, true,  false>, cudaFuncAttributeMaxDynamicSharedMemorySize, SM_MAIN);
    cudaFuncSetAttribute(mma_gemm<128, 1, false, false>, cudaFuncAttributeMaxDynamicSharedMemorySize, SM_MAIN);
    cudaFuncSetAttribute(mma_gemm<64,  0, false, true >, cudaFuncAttributeMaxDynamicSharedMemorySize, SM_MAIN);
    cudaFuncSetAttribute(mma_gemm<64,  0, true,  false>, cudaFuncAttributeMaxDynamicSharedMemorySize, SM_OUT);

    const int M = MROWS;
    dim3 blk(256);
    dim3 g512(HIDDEN / 128, M / 128);     // (4, 256)
    dim3 gdual(HIDDEN / 64, M / 128);     // (8, 256)
    dim3 gout(1, M / 128);

    prep0_kernel<<<64, 256>>>(embW, outW);

    // embedding: h = x @ embWt^T + embb
    mma_gemm<128, 0, true, false><<<g512, blk, SM_MAIN>>>(
        x, embWt, nullptr, embb, nullptr, bufh, M, HIDDEN, DIN, nullptr, nullptr);

    for (int l = 0; l < NLAYERS; l++) {
        prep_kernel<<<128, 256>>>(nu + l * STATE, th + l * STATE, ga + l * STATE,
                                  Bre + (size_t)l * STATE * HIDDEN,
                                  Bim + (size_t)l * STATE * HIDDEN,
                                  Cre + (size_t)l * HIDDEN * STATE,
                                  Cim + (size_t)l * HIDDEN * STATE,
                                  W1 + (size_t)l * HIDDEN * HIDDEN,
                                  W2 + (size_t)l * HIDDEN * HIDDEN);

        // Bu = h @ Bn^T -> bufa  (M x 2S, re/im interleaved)
        mma_gemm<128, 0, true, false><<<g512, blk, SM_MAIN>>>(
            bufh, Bn, nullptr, nullptr, nullptr, bufa, M, 2 * STATE, HIDDEN, nullptr, nullptr);

        // chunked diagonal complex scan: bufa -> bufb (tf32-rounded)
        scanA_kernel<<<1024, 256>>>(bufa);
        scanB_kernel<<<16, 256>>>();
        scanC_kernel<<<1024, 256>>>(bufa, bufb);

        // y = tfround(gelu( Hs @ Wc^T + h*D )) -> bufa
        mma_gemm<128, 1, false, false><<<g512, blk, SM_MAIN>>>(
            bufb, Wc, nullptr, nullptr, nullptr, bufa, M, HIDDEN, 2 * STATE, bufh, Dv + l * HIDDEN);

        // h = (y@W1t + b1) * sigmoid(y@W2t + b2) + h   (fused dual GEMM, in-place bufh)
        mma_gemm<64, 0, false, true><<<gdual, blk, SM_MAIN>>>(
            bufa, W1t, W2t, b1 + l * HIDDEN, b2 + l * HIDDEN, bufh,
            M, HIDDEN, HIDDEN, bufh, nullptr);
    }

    // out = h @ outWt^T + outb
    mma_gemm<64, 0, true, false><<<gout, blk, SM_OUT>>>(
        bufh, outWt, nullptr, outb, nullptr, out, M, DOUT, HIDDEN, nullptr, nullptr);
}

// round 10
// speedup vs baseline: 10.7949x; 1.5160x over previous
#include <cuda_runtime.h>
#include <cuda_fp16.h>
#include <cstdint>
#include <math.h>

#define BATCH   16
#define SEQ     2048
#define DIN     128
#define HIDDEN  512
#define STATE   256
#define DOUT    64
#define NLAYERS 4
#define MROWS   (BATCH * SEQ)   /* 32768 */
#define NCH     64
#define CLEN    (SEQ / NCH)     /* 32 */

// ---------------- scratch (allocation-free: __device__ globals) ----------------
__device__ float  g_bufh[(size_t)MROWS * HIDDEN];            // residual stream h (fp32)
__device__ float  g_bufa[(size_t)MROWS * HIDDEN];            // Bu (fp32, scan input)
__device__ __align__(16) __half g_h16 [(size_t)MROWS * HIDDEN];  // h   (GEMM A)
__device__ __align__(16) __half g_y16 [(size_t)MROWS * HIDDEN];  // y   (GEMM A)
__device__ __align__(16) __half g_hs16[(size_t)MROWS * HIDDEN];  // Hs  (GEMM A)
__device__ __align__(16) __half g_x16 [(size_t)MROWS * DIN];     // x   (GEMM A)
__device__ __align__(16) __half g_Bn [2 * STATE * HIDDEN];   // rows interleaved 2s/2s+1
__device__ __align__(16) __half g_Wc [HIDDEN * 2 * STATE];   // cols interleaved Cre/-Cim
__device__ __align__(16) __half g_W1h[HIDDEN * HIDDEN];
__device__ __align__(16) __half g_W2h[HIDDEN * HIDDEN];
__device__ __align__(16) __half g_embWh[HIDDEN * DIN];
__device__ __align__(16) __half g_outWh[DOUT * HIDDEN];
__device__ float2 g_lam2[STATE];
__device__ float2 g_carry[BATCH * NCH * STATE];
__device__ float2 g_cin  [BATCH * NCH * STATE];

// ---------------- mma helpers ----------------
__device__ __forceinline__ void mma_f16(float* d, const uint32_t* a, const uint32_t* b) {
    asm volatile(
        "mma.sync.aligned.m16n8k16.row.col.f32.f16.f16.f32 "
        "{%0,%1,%2,%3}, {%4,%5,%6,%7}, {%8,%9}, {%0,%1,%2,%3};"
        : "+f"(d[0]), "+f"(d[1]), "+f"(d[2]), "+f"(d[3])
        : "r"(a[0]), "r"(a[1]), "r"(a[2]), "r"(a[3]), "r"(b[0]), "r"(b[1]));
}
__device__ __forceinline__ void ldsm4(uint32_t& r0, uint32_t& r1, uint32_t& r2, uint32_t& r3,
                                      uint32_t addr) {
    asm volatile("ldmatrix.sync.aligned.m8n8.x4.shared.b16 {%0,%1,%2,%3}, [%4];"
        : "=r"(r0), "=r"(r1), "=r"(r2), "=r"(r3) : "r"(addr));
}
__device__ __forceinline__ void cp16(void* s, const void* g) {
    uint32_t sa = (uint32_t)__cvta_generic_to_shared(s);
    asm volatile("cp.async.cg.shared.global [%0], [%1], 16;" :: "r"(sa), "l"(g));
}
#define CP_COMMIT() asm volatile("cp.async.commit_group;" ::: "memory")
#define CP_WAIT(n)  asm volatile("cp.async.wait_group %0;" :: "n"(n) : "memory")

// ---------------- one-time conversions ----------------
__global__ void prep0_kernel(const float* __restrict__ x, const float* __restrict__ embW,
                             const float* __restrict__ outW)
{
    int tid = blockIdx.x * blockDim.x + threadIdx.x;
    int stride = gridDim.x * blockDim.x;
    for (int i = tid; i < MROWS * DIN; i += stride) g_x16[i] = __float2half_rn(x[i]);
    for (int i = tid; i < HIDDEN * DIN; i += stride) g_embWh[i] = __float2half_rn(embW[i]);
    for (int i = tid; i < DOUT * HIDDEN; i += stride) g_outWh[i] = __float2half_rn(outW[i]);
}

// ---------------- per-layer small precompute ----------------
__global__ void prep_kernel(const float* __restrict__ nu, const float* __restrict__ th,
                            const float* __restrict__ ga,
                            const float* __restrict__ Bre, const float* __restrict__ Bim,
                            const float* __restrict__ Cre, const float* __restrict__ Cim,
                            const float* __restrict__ W1, const float* __restrict__ W2)
{
    int tid = blockIdx.x * blockDim.x + threadIdx.x;
    int stride = gridDim.x * blockDim.x;
    if (tid < STATE) {
        float mag = expf(-expf(nu[tid]));
        float ang = expf(th[tid]);
        g_lam2[tid] = make_float2(mag * cosf(ang), mag * sinf(ang));
    }
    for (int idx = tid; idx < STATE * HIDDEN; idx += stride) {
        int s = idx / HIDDEN, h = idx % HIDDEN;
        float g = expf(ga[s]);
        g_Bn[(size_t)(2 * s)     * HIDDEN + h] = __float2half_rn(Bre[idx] * g);
        g_Bn[(size_t)(2 * s + 1) * HIDDEN + h] = __float2half_rn(Bim[idx] * g);
    }
    for (int idx = tid; idx < HIDDEN * STATE; idx += stride) {
        int h = idx / STATE, s = idx % STATE;
        g_Wc[(size_t)h * (2 * STATE) + 2 * s]     = __float2half_rn( Cre[idx]);
        g_Wc[(size_t)h * (2 * STATE) + 2 * s + 1] = __float2half_rn(-Cim[idx]);
    }
    for (int idx = tid; idx < HIDDEN * HIDDEN; idx += stride) {
        g_W1h[idx] = __float2half_rn(W1[idx]);
        g_W2h[idx] = __float2half_rn(W2[idx]);
    }
}

// ---------------- chunked diagonal complex scan (fp32) ----------------
__global__ void scanA_kernel(const float* __restrict__ Bu)
{
    int t = blockIdx.x * blockDim.x + threadIdx.x;   // 262144
    int s  = t & (STATE - 1);
    int ch = (t >> 8) & (NCH - 1);
    int b  = t >> 14;
    float2 l = g_lam2[s];
    const float2* src = (const float2*)Bu + ((size_t)(b * SEQ + ch * CLEN)) * STATE + s;
    float hr = 0.f, hi = 0.f;
#pragma unroll 4
    for (int i = 0; i < CLEN; i++) {
        float2 u = src[(size_t)i * STATE];
        float nr = fmaf(l.x, hr, fmaf(-l.y, hi, u.x));
        float ni = fmaf(l.x, hi, fmaf( l.y, hr, u.y));
        hr = nr; hi = ni;
    }
    g_carry[(b * NCH + ch) * STATE + s] = make_float2(hr, hi);
}

__global__ void scanB_kernel()
{
    int t = blockIdx.x * blockDim.x + threadIdx.x;   // 4096
    int s = t & (STATE - 1);
    int b = t >> 8;
    float2 l = g_lam2[s];
    float pr = l.x, pi = l.y;
#pragma unroll
    for (int k = 0; k < 5; k++) {                    // lam^32
        float nr = pr * pr - pi * pi;
        float ni = 2.f * pr * pi;
        pr = nr; pi = ni;
    }
    float hr = 0.f, hi = 0.f;
#pragma unroll
    for (int ch = 0; ch < NCH; ch++) {
        g_cin[(b * NCH + ch) * STATE + s] = make_float2(hr, hi);
        float2 c = g_carry[(b * NCH + ch) * STATE + s];
        float nr = pr * hr - pi * hi + c.x;
        float ni = pr * hi + pi * hr + c.y;
        hr = nr; hi = ni;
    }
}

__global__ void scanC_kernel(const float* __restrict__ Bu, __half* __restrict__ Hs16)
{
    int t = blockIdx.x * blockDim.x + threadIdx.x;
    int s  = t & (STATE - 1);
    int ch = (t >> 8) & (NCH - 1);
    int b  = t >> 14;
    float2 l = g_lam2[s];
    size_t base = ((size_t)(b * SEQ + ch * CLEN)) * STATE + s;
    const float2* src = (const float2*)Bu + base;
    __half2* dst = (__half2*)Hs16 + base;
    float2 h0 = g_cin[(b * NCH + ch) * STATE + s];
    float hr = h0.x, hi = h0.y;
#pragma unroll 4
    for (int i = 0; i < CLEN; i++) {
        float2 u = src[(size_t)i * STATE];
        float nr = fmaf(l.x, hr, fmaf(-l.y, hi, u.x));
        float ni = fmaf(l.x, hi, fmaf( l.y, hr, u.y));
        hr = nr; hi = ni;
        dst[(size_t)i * STATE] = __floats2half2_rn(hr, hi);   // feeds GEMM A only
    }
}

// ---------------- pipelined fp16 MMA GEMM: C = A @ W^T (+ epilogue) ----------------
// EPI 0: v = acc (+bias[col])
// EPI 1: v = gelu_exact(acc + e1[o]*e2[col])
// DUAL : v = (acc+bias) * sigmoid(acc2+bias2) + e1[o]
// Outputs: Cf (fp32) if non-null, C16 (half) if non-null.
template <int BN, int EPI, bool DUAL>
__global__ void __launch_bounds__(256, 2)
mma_gemm(const __half* __restrict__ A, const __half* __restrict__ W,
         const __half* __restrict__ W2p,
         const float* __restrict__ bias, const float* __restrict__ bias2,
         float* __restrict__ Cf, __half* __restrict__ C16,
         int M, int N, int K,
         const float* __restrict__ e1, const float* __restrict__ e2)
{
    constexpr int BM = 128, BK = 64, RS = BK + 8;     // row stride = 72 halves (144 B)
    constexpr int STAGES = 3;
    constexpr int WN = BN / 2, NFR = WN / 8, NPAIR = NFR / 2;
    constexpr int NBTILE = DUAL ? 2 * BN : BN;
    constexpr int STAGE_H = (BM + NBTILE) * RS;       // halves per stage
    constexpr int STAGE_B = STAGE_H * 2;              // bytes per stage
    constexpr int BCH = BN / 32;                      // B cp.async chunks per thread

    extern __shared__ __half smemh[];

    const int tid = threadIdx.x;
    const int wid = tid >> 5, lane = tid & 31;
    const int g = lane >> 2, tig = lane & 3;
    const int warp_m = wid & 3, warp_n = wid >> 2;    // 4 x 2
    const int bm = blockIdx.y * BM;
    const int bn = blockIdx.x * BN;

    // ldmatrix lane addressing
    const int t8 = lane >> 3, w8 = lane & 7;
    const uint32_t sb0 = (uint32_t)__cvta_generic_to_shared(smemh);
    // A: tile t -> rows +8*(t&1), k +8*(t>>1) halves
    const int arow = warp_m * 32 + (t8 & 1) * 8 + w8;
    uint32_t aoff[2];
    aoff[0] = (uint32_t)((arow * RS + (t8 >> 1) * 8) * 2);
    aoff[1] = aoff[0] + 16 * RS * 2;
    // B: tile t -> col +8*(t>>1), k +8*(t&1) halves
    uint32_t boff[NPAIR];
#pragma unroll
    for (int p = 0; p < NPAIR; p++) {
        int col = warp_n * WN + p * 16 + (t8 >> 1) * 8 + w8;
        boff[p] = (uint32_t)(((BM + col) * RS + (t8 & 1) * 8) * 2);
    }
    constexpr uint32_t B2OFF = (uint32_t)(BN * RS * 2);

    float acc[2][NFR][4];
    float acc2[DUAL ? 2 : 1][DUAL ? NFR : 1][4];
#pragma unroll
    for (int mi = 0; mi < 2; mi++)
#pragma unroll
        for (int ni = 0; ni < NFR; ni++)
#pragma unroll
            for (int j = 0; j < 4; j++) {
                acc[mi][ni][j] = 0.f;
                if (DUAL) acc2[mi][ni][j] = 0.f;
            }

    const int nkb = K / BK;

    auto issue = [&](int kb, int slot) {
        __half* Sb = smemh + slot * STAGE_H;
        const __half* Ag = A + (size_t)bm * K + kb * BK;
#pragma unroll
        for (int i = 0; i < 4; i++) {                 // 128 rows x 8 chunks = 1024
            int c = tid + i * 256;
            int r = c >> 3, kc = c & 7;
            cp16(Sb + r * RS + kc * 8, Ag + (size_t)r * K + kc * 8);
        }
        const __half* Wg = W + (size_t)bn * K + kb * BK;
        __half* Bb = Sb + BM * RS;
#pragma unroll
        for (int i = 0; i < BCH; i++) {
            int c = tid + i * 256;
            int r = c >> 3, kc = c & 7;
            cp16(Bb + r * RS + kc * 8, Wg + (size_t)r * K + kc * 8);
        }
        if (DUAL) {
            const __half* W2g = W2p + (size_t)bn * K + kb * BK;
            __half* B2b = Sb + (BM + BN) * RS;
#pragma unroll
            for (int i = 0; i < BCH; i++) {
                int c = tid + i * 256;
                int r = c >> 3, kc = c & 7;
                cp16(B2b + r * RS + kc * 8, W2g + (size_t)r * K + kc * 8);
            }
        }
    };

#pragma unroll
    for (int s = 0; s < STAGES - 1; s++) {
        if (s < nkb) issue(s, s);
        CP_COMMIT();
    }

    int rslot = 0, wslot = STAGES - 1;
    for (int kb = 0; kb < nkb; kb++) {
        CP_WAIT(STAGES - 2);
        __syncthreads();
        if (kb + STAGES - 1 < nkb) issue(kb + STAGES - 1, wslot);
        CP_COMMIT();
        if (++wslot == STAGES) wslot = 0;

        const uint32_t sbs = sb0 + rslot * STAGE_B;
#pragma unroll
        for (int ks = 0; ks < 4; ks++) {              // 4 x k16 per K64 block
            uint32_t afr[2][4];
#pragma unroll
            for (int mi = 0; mi < 2; mi++)
                ldsm4(afr[mi][0], afr[mi][1], afr[mi][2], afr[mi][3],
                      sbs + aoff[mi] + ks * 32);
            uint32_t bfr[NFR][2];
            uint32_t bfr2[DUAL ? NFR : 1][2];
#pragma unroll
            for (int p = 0; p < NPAIR; p++) {
                uint32_t r0, r1, r2, r3;
                ldsm4(r0, r1, r2, r3, sbs + boff[p] + ks * 32);
                bfr[2 * p][0] = r0; bfr[2 * p][1] = r1;
                bfr[2 * p + 1][0] = r2; bfr[2 * p + 1][1] = r3;
                if (DUAL) {
                    ldsm4(r0, r1, r2, r3, sbs + boff[p] + B2OFF + ks * 32);
                    bfr2[2 * p][0] = r0; bfr2[2 * p][1] = r1;
                    bfr2[2 * p + 1][0] = r2; bfr2[2 * p + 1][1] = r3;
                }
            }
#pragma unroll
            for (int mi = 0; mi < 2; mi++)
#pragma unroll
                for (int ni = 0; ni < NFR; ni++) {
                    mma_f16(acc[mi][ni], afr[mi], bfr[ni]);
                    if (DUAL) mma_f16(acc2[mi][ni], afr[mi], bfr2[ni]);
                }
        }
        if (++rslot == STAGES) rslot = 0;
    }

    // -------- epilogue --------
#pragma unroll
    for (int mi = 0; mi < 2; mi++) {
        int row0 = bm + warp_m * 32 + mi * 16 + g;
        int row1 = row0 + 8;
#pragma unroll
        for (int ni = 0; ni < NFR; ni++) {
            int col = bn + warp_n * WN + ni * 8 + tig * 2;
            size_t o0 = (size_t)row0 * N + col;
            size_t o1 = (size_t)row1 * N + col;
            float r0 = acc[mi][ni][0], r1 = acc[mi][ni][1];
            float r2 = acc[mi][ni][2], r3 = acc[mi][ni][3];
            float2 v0, v1;
            if (DUAL) {
                float b10 = bias[col], b11 = bias[col + 1];
                float b20 = bias2[col], b21 = bias2[col + 1];
                float q0 = acc2[mi][ni][0], q1 = acc2[mi][ni][1];
                float q2 = acc2[mi][ni][2], q3 = acc2[mi][ni][3];
                float s0 = 1.f / (1.f + expf(-(q0 + b20)));
                float s1 = 1.f / (1.f + expf(-(q1 + b21)));
                float s2 = 1.f / (1.f + expf(-(q2 + b20)));
                float s3 = 1.f / (1.f + expf(-(q3 + b21)));
                v0 = make_float2(fmaf(r0 + b10, s0, e1[o0]), fmaf(r1 + b11, s1, e1[o0 + 1]));
                v1 = make_float2(fmaf(r2 + b10, s2, e1[o1]), fmaf(r3 + b11, s3, e1[o1 + 1]));
            } else if (EPI == 0) {
                float b0 = bias ? bias[col] : 0.f;
                float b1 = bias ? bias[col + 1] : 0.f;
                v0 = make_float2(r0 + b0, r1 + b1);
                v1 = make_float2(r2 + b0, r3 + b1);
            } else {
                float d0 = e2[col], d1 = e2[col + 1];
                float t0 = r0 + e1[o0] * d0;
                float t1 = r1 + e1[o0 + 1] * d1;
                float t2 = r2 + e1[o1] * d0;
                float t3 = r3 + e1[o1 + 1] * d1;
                v0 = make_float2(t0 * normcdff(t0), t1 * normcdff(t1));
                v1 = make_float2(t2 * normcdff(t2), t3 * normcdff(t3));
            }
            if (Cf) {
                *(float2*)(Cf + o0) = v0;
                *(float2*)(Cf + o1) = v1;
            }
            if (C16) {
                *(__half2*)(C16 + o0) = __floats2half2_rn(v0.x, v0.y);
                *(__half2*)(C16 + o1) = __floats2half2_rn(v1.x, v1.y);
            }
        }
    }
}

// ---------------- launcher ----------------
extern "C" void kernel_launch(void* const* d_in, const int* in_sizes, int n_in,
                              void* d_out, int out_size)
{
    const float* x    = (const float*)d_in[0];
    const float* embW = (const float*)d_in[1];
    const float* embb = (const float*)d_in[2];
    const float* nu   = (const float*)d_in[3];
    const float* th   = (const float*)d_in[4];
    const float* ga   = (const float*)d_in[5];
    const float* Bre  = (const float*)d_in[6];
    const float* Bim  = (const float*)d_in[7];
    const float* Cre  = (const float*)d_in[8];
    const float* Cim  = (const float*)d_in[9];
    const float* Dv   = (const float*)d_in[10];
    const float* W1   = (const float*)d_in[11];
    const float* b1   = (const float*)d_in[12];
    const float* W2   = (const float*)d_in[13];
    const float* b2   = (const float*)d_in[14];
    const float* outW = (const float*)d_in[15];
    const float* outb = (const float*)d_in[16];
    float* out = (float*)d_out;
    (void)in_sizes; (void)n_in; (void)out_size;

    float *bufh, *bufa;
    __half *h16, *y16, *hs16, *x16, *Bn, *Wc, *W1h, *W2h, *embWh, *outWh;
    cudaGetSymbolAddress((void**)&bufh, g_bufh);
    cudaGetSymbolAddress((void**)&bufa, g_bufa);
    cudaGetSymbolAddress((void**)&h16,  g_h16);
    cudaGetSymbolAddress((void**)&y16,  g_y16);
    cudaGetSymbolAddress((void**)&hs16, g_hs16);
    cudaGetSymbolAddress((void**)&x16,  g_x16);
    cudaGetSymbolAddress((void**)&Bn,   g_Bn);
    cudaGetSymbolAddress((void**)&Wc,   g_Wc);
    cudaGetSymbolAddress((void**)&W1h,  g_W1h);
    cudaGetSymbolAddress((void**)&W2h,  g_W2h);
    cudaGetSymbolAddress((void**)&embWh, g_embWh);
    cudaGetSymbolAddress((void**)&outWh, g_outWh);

    // smem: (BM + NBTILE) * 72 halves * 3 stages * 2B
    const int SM_MAIN = (128 + 128) * 72 * 3 * 2;   // 110592
    const int SM_OUT  = (128 + 64) * 72 * 3 * 2;    // 82944
    cudaFuncSetAttribute(mma_gemm<128, 0, false>, cudaFuncAttributeMaxDynamicSharedMemorySize, SM_MAIN);
    cudaFuncSetAttribute(mma_gemm<128, 1, false>, cudaFuncAttributeMaxDynamicSharedMemorySize, SM_MAIN);
    cudaFuncSetAttribute(mma_gemm<64,  0, true >, cudaFuncAttributeMaxDynamicSharedMemorySize, SM_MAIN);
    cudaFuncSetAttribute(mma_gemm<64,  0, false>, cudaFuncAttributeMaxDynamicSharedMemorySize, SM_OUT);

    const int M = MROWS;
    dim3 blk(256);
    dim3 g512(HIDDEN / 128, M / 128);     // (4, 256)
    dim3 gdual(HIDDEN / 64, M / 128);     // (8, 256)
    dim3 gout(1, M / 128);

    prep0_kernel<<<256, 256>>>(x, embW, outW);

    // embedding: h = x @ embW^T + embb  -> bufh (fp32) + h16
    mma_gemm<128, 0, false><<<g512, blk, SM_MAIN>>>(
        x16, embWh, nullptr, embb, nullptr, bufh, h16, M, HIDDEN, DIN, nullptr, nullptr);

    for (int l = 0; l < NLAYERS; l++) {
        prep_kernel<<<128, 256>>>(nu + l * STATE, th + l * STATE, ga + l * STATE,
                                  Bre + (size_t)l * STATE * HIDDEN,
                                  Bim + (size_t)l * STATE * HIDDEN,
                                  Cre + (size_t)l * HIDDEN * STATE,
                                  Cim + (size_t)l * HIDDEN * STATE,
                                  W1 + (size_t)l * HIDDEN * HIDDEN,
                                  W2 + (size_t)l * HIDDEN * HIDDEN);

        // Bu = h @ Bn^T -> bufa (fp32, re/im interleaved)
        mma_gemm<128, 0, false><<<g512, blk, SM_MAIN>>>(
            h16, Bn, nullptr, nullptr, nullptr, bufa, nullptr, M, 2 * STATE, HIDDEN,
            nullptr, nullptr);

        // chunked diagonal complex scan: bufa -> hs16
        scanA_kernel<<<1024, 256>>>(bufa);
        scanB_kernel<<<16, 256>>>();
        scanC_kernel<<<1024, 256>>>(bufa, hs16);

        // y = gelu( Hs @ Wc^T + h*D ) -> y16
        mma_gemm<128, 1, false><<<g512, blk, SM_MAIN>>>(
            hs16, Wc, nullptr, nullptr, nullptr, nullptr, y16, M, HIDDEN, 2 * STATE,
            bufh, Dv + l * HIDDEN);

        // h = (y@W1 + b1) * sigmoid(y@W2 + b2) + h  -> bufh (fp32) + h16
        mma_gemm<64, 0, true><<<gdual, blk, SM_MAIN>>>(
            y16, W1h, W2h, b1 + l * HIDDEN, b2 + l * HIDDEN, bufh, h16,
            M, HIDDEN, HIDDEN, bufh, nullptr);
    }

    // out = h @ outW^T + outb
    mma_gemm<64, 0, false><<<gout, blk, SM_OUT>>>(
        h16, outWh, nullptr, outb, nullptr, out, nullptr, M, DOUT, HIDDEN,
        nullptr, nullptr);
}

// round 12
// speedup vs baseline: 11.0914x; 1.0275x over previous
#include <cuda_runtime.h>
#include <cuda_fp16.h>
#include <cstdint>
#include <math.h>

#define BATCH   16
#define SEQ     2048
#define DIN     128
#define HIDDEN  512
#define STATE   256
#define DOUT    64
#define NLAYERS 4
#define MROWS   (BATCH * SEQ)   /* 32768 */
#define NCH     64
#define CLEN    (SEQ / NCH)     /* 32 */

// ---------------- scratch (allocation-free: __device__ globals) ----------------
__device__ float  g_bufh[(size_t)MROWS * HIDDEN];            // residual stream h (fp32)
__device__ float  g_bufa[(size_t)MROWS * HIDDEN];            // local-scan output (fp32)
__device__ __align__(16) __half g_h16 [(size_t)MROWS * HIDDEN];  // h   (GEMM A)
__device__ __align__(16) __half g_y16 [(size_t)MROWS * HIDDEN];  // y   (GEMM A)
__device__ __align__(16) __half g_hs16[(size_t)MROWS * HIDDEN];  // Hs  (GEMM A)
__device__ __align__(16) __half g_x16 [(size_t)MROWS * DIN];     // x   (GEMM A)
__device__ __align__(16) __half g_Bn [(size_t)NLAYERS * 2 * STATE * HIDDEN];
__device__ __align__(16) __half g_Wc [(size_t)NLAYERS * HIDDEN * 2 * STATE];
__device__ __align__(16) __half g_W1h[(size_t)NLAYERS * HIDDEN * HIDDEN];
__device__ __align__(16) __half g_W2h[(size_t)NLAYERS * HIDDEN * HIDDEN];
__device__ __align__(16) __half g_embWh[HIDDEN * DIN];
__device__ __align__(16) __half g_outWh[DOUT * HIDDEN];
__device__ float2 g_lam2[NLAYERS * STATE];
__device__ float2 g_carry[BATCH * NCH * STATE];
__device__ float2 g_cin  [BATCH * NCH * STATE];

// ---------------- mma helpers ----------------
__device__ __forceinline__ void mma_f16(float* d, const uint32_t* a, const uint32_t* b) {
    asm volatile(
        "mma.sync.aligned.m16n8k16.row.col.f32.f16.f16.f32 "
        "{%0,%1,%2,%3}, {%4,%5,%6,%7}, {%8,%9}, {%0,%1,%2,%3};"
        : "+f"(d[0]), "+f"(d[1]), "+f"(d[2]), "+f"(d[3])
        : "r"(a[0]), "r"(a[1]), "r"(a[2]), "r"(a[3]), "r"(b[0]), "r"(b[1]));
}
__device__ __forceinline__ void ldsm4(uint32_t& r0, uint32_t& r1, uint32_t& r2, uint32_t& r3,
                                      uint32_t addr) {
    asm volatile("ldmatrix.sync.aligned.m8n8.x4.shared.b16 {%0,%1,%2,%3}, [%4];"
        : "=r"(r0), "=r"(r1), "=r"(r2), "=r"(r3) : "r"(addr));
}
__device__ __forceinline__ void cp16(void* s, const void* g) {
    uint32_t sa = (uint32_t)__cvta_generic_to_shared(s);
    asm volatile("cp.async.cg.shared.global [%0], [%1], 16;" :: "r"(sa), "l"(g));
}
#define CP_COMMIT() asm volatile("cp.async.commit_group;" ::: "memory")
#define CP_WAIT(n)  asm volatile("cp.async.wait_group %0;" :: "n"(n) : "memory")

// ---------------- one-time conversions (all layers) ----------------
__global__ void prep_all_kernel(const float* __restrict__ x,
                                const float* __restrict__ embW,
                                const float* __restrict__ outW,
                                const float* __restrict__ nu, const float* __restrict__ th,
                                const float* __restrict__ ga,
                                const float* __restrict__ Bre, const float* __restrict__ Bim,
                                const float* __restrict__ Cre, const float* __restrict__ Cim,
                                const float* __restrict__ W1, const float* __restrict__ W2)
{
    int tid = blockIdx.x * blockDim.x + threadIdx.x;
    int stride = gridDim.x * blockDim.x;
    for (int i = tid; i < MROWS * DIN; i += stride) g_x16[i] = __float2half_rn(x[i]);
    for (int i = tid; i < HIDDEN * DIN; i += stride) g_embWh[i] = __float2half_rn(embW[i]);
    for (int i = tid; i < DOUT * HIDDEN; i += stride) g_outWh[i] = __float2half_rn(outW[i]);
    for (int i = tid; i < NLAYERS * STATE; i += stride) {
        float mag = expf(-expf(nu[i]));
        float ang = expf(th[i]);
        g_lam2[i] = make_float2(mag * cosf(ang), mag * sinf(ang));
    }
    for (int idx = tid; idx < NLAYERS * STATE * HIDDEN; idx += stride) {
        int l = idx / (STATE * HIDDEN);
        int r = idx % (STATE * HIDDEN);
        int s = r / HIDDEN, h = r % HIDDEN;
        float g = expf(ga[l * STATE + s]);
        size_t base = (size_t)l * 2 * STATE * HIDDEN;
        g_Bn[base + (size_t)(2 * s)     * HIDDEN + h] = __float2half_rn(Bre[idx] * g);
        g_Bn[base + (size_t)(2 * s + 1) * HIDDEN + h] = __float2half_rn(Bim[idx] * g);
    }
    for (int idx = tid; idx < NLAYERS * HIDDEN * STATE; idx += stride) {
        int l = idx / (HIDDEN * STATE);
        int r = idx % (HIDDEN * STATE);
        int h = r / STATE, s = r % STATE;
        size_t base = (size_t)l * HIDDEN * 2 * STATE;
        g_Wc[base + (size_t)h * (2 * STATE) + 2 * s]     = __float2half_rn( Cre[idx]);
        g_Wc[base + (size_t)h * (2 * STATE) + 2 * s + 1] = __float2half_rn(-Cim[idx]);
    }
    for (int idx = tid; idx < NLAYERS * HIDDEN * HIDDEN; idx += stride) {
        g_W1h[idx] = __float2half_rn(W1[idx]);
        g_W2h[idx] = __float2half_rn(W2[idx]);
    }
}

// ---------------- carry combine across chunks ----------------
__global__ void scanB_kernel(const float2* __restrict__ lamp)
{
    int t = blockIdx.x * blockDim.x + threadIdx.x;   // 4096
    int s = t & (STATE - 1);
    int b = t >> 8;
    float2 l = lamp[s];
    float pr = l.x, pi = l.y;
#pragma unroll
    for (int k = 0; k < 5; k++) {                    // lam^32
        float nr = pr * pr - pi * pi;
        float ni = 2.f * pr * pi;
        pr = nr; pi = ni;
    }
    float hr = 0.f, hi = 0.f;
#pragma unroll
    for (int ch = 0; ch < NCH; ch++) {
        g_cin[(b * NCH + ch) * STATE + s] = make_float2(hr, hi);
        float2 c = g_carry[(b * NCH + ch) * STATE + s];
        float nr = pr * hr - pi * hi + c.x;
        float ni = pr * hi + pi * hr + c.y;
        hr = nr; hi = ni;
    }
}

// ---------------- carry correction: Hs_t = local_t + lam^{i+1} * H_in ----------------
__global__ void scanC_kernel(const float* __restrict__ local, __half* __restrict__ Hs16,
                             const float2* __restrict__ lamp)
{
    int t = blockIdx.x * blockDim.x + threadIdx.x;
    int s  = t & (STATE - 1);
    int ch = (t >> 8) & (NCH - 1);
    int b  = t >> 14;
    float2 l = lamp[s];
    size_t base = ((size_t)(b * SEQ + ch * CLEN)) * STATE + s;
    const float2* src = (const float2*)local + base;
    __half2* dst = (__half2*)Hs16 + base;
    float2 H = g_cin[(b * NCH + ch) * STATE + s];
    float cpr = l.x, cpi = l.y;                      // lam^1
#pragma unroll 4
    for (int i = 0; i < CLEN; i++) {
        float2 lo = src[(size_t)i * STATE];
        float hr = lo.x + cpr * H.x - cpi * H.y;
        float hi = lo.y + cpr * H.y + cpi * H.x;
        dst[(size_t)i * STATE] = __floats2half2_rn(hr, hi);
        float nr = cpr * l.x - cpi * l.y;
        cpi = cpr * l.y + cpi * l.x;
        cpr = nr;
    }
}

// ---------------- pipelined fp16 MMA GEMM: C = A @ W^T (+ epilogue) ----------------
// EPI 0: v = acc (+bias[col])
// EPI 1: v = gelu_exact(acc + e1h[o]*e2[col])
// EPI 2: fused chunk-local scan (Bu GEMM): local scan -> Cf (float2), carries -> g_carry
// DUAL : v = (acc+bias) * sigmoid(acc2+bias2) + e1[o]
template <int BN, int EPI, bool DUAL>
__global__ void __launch_bounds__(256, 2)
mma_gemm(const __half* __restrict__ A, const __half* __restrict__ W,
         const __half* __restrict__ W2p,
         const float* __restrict__ bias, const float* __restrict__ bias2,
         float* __restrict__ Cf, __half* __restrict__ C16,
         int M, int N, int K,
         const float* __restrict__ e1, const __half* __restrict__ e1h,
         const float* __restrict__ e2, const float2* __restrict__ lamp)
{
    constexpr int BM = 128, BK = 64, RS = BK + 8;     // row stride = 72 halves (144 B)
    constexpr int STAGES = 3;
    constexpr int WN = BN / 2, NFR = WN / 8, NPAIR = NFR / 2;
    constexpr int NBTILE = DUAL ? 2 * BN : BN;
    constexpr int STAGE_H = (BM + NBTILE) * RS;       // halves per stage
    constexpr int STAGE_B = STAGE_H * 2;              // bytes per stage
    constexpr int BCH = BN / 32;

    extern __shared__ __half smemh[];

    const int tid = threadIdx.x;
    const int wid = tid >> 5, lane = tid & 31;
    const int g = lane >> 2, tig = lane & 3;
    const int warp_m = wid & 3, warp_n = wid >> 2;    // 4 x 2
    const int bm = blockIdx.y * BM;
    const int bn = blockIdx.x * BN;

    const int t8 = lane >> 3, w8 = lane & 7;
    const uint32_t sb0 = (uint32_t)__cvta_generic_to_shared(smemh);
    const int arow = warp_m * 32 + (t8 & 1) * 8 + w8;
    uint32_t aoff[2];
    aoff[0] = (uint32_t)((arow * RS + (t8 >> 1) * 8) * 2);
    aoff[1] = aoff[0] + 16 * RS * 2;
    uint32_t boff[NPAIR];
#pragma unroll
    for (int p = 0; p < NPAIR; p++) {
        int col = warp_n * WN + p * 16 + (t8 >> 1) * 8 + w8;
        boff[p] = (uint32_t)(((BM + col) * RS + (t8 & 1) * 8) * 2);
    }
    constexpr uint32_t B2OFF = (uint32_t)(BN * RS * 2);

    float acc[2][NFR][4];
    float acc2[DUAL ? 2 : 1][DUAL ? NFR : 1][4];
#pragma unroll
    for (int mi = 0; mi < 2; mi++)
#pragma unroll
        for (int ni = 0; ni < NFR; ni++)
#pragma unroll
            for (int j = 0; j < 4; j++) {
                acc[mi][ni][j] = 0.f;
                if (DUAL) acc2[mi][ni][j] = 0.f;
            }

    const int nkb = K / BK;

    auto issue = [&](int kb, int slot) {
        __half* Sb = smemh + slot * STAGE_H;
        const __half* Ag = A + (size_t)bm * K + kb * BK;
#pragma unroll
        for (int i = 0; i < 4; i++) {
            int c = tid + i * 256;
            int r = c >> 3, kc = c & 7;
            cp16(Sb + r * RS + kc * 8, Ag + (size_t)r * K + kc * 8);
        }
        const __half* Wg = W + (size_t)bn * K + kb * BK;
        __half* Bb = Sb + BM * RS;
#pragma unroll
        for (int i = 0; i < BCH; i++) {
            int c = tid + i * 256;
            int r = c >> 3, kc = c & 7;
            cp16(Bb + r * RS + kc * 8, Wg + (size_t)r * K + kc * 8);
        }
        if (DUAL) {
            const __half* W2g = W2p + (size_t)bn * K + kb * BK;
            __half* B2b = Sb + (BM + BN) * RS;
#pragma unroll
            for (int i = 0; i < BCH; i++) {
                int c = tid + i * 256;
                int r = c >> 3, kc = c & 7;
                cp16(B2b + r * RS + kc * 8, W2g + (size_t)r * K + kc * 8);
            }
        }
    };

#pragma unroll
    for (int s = 0; s < STAGES - 1; s++) {
        if (s < nkb) issue(s, s);
        CP_COMMIT();
    }

    int rslot = 0, wslot = STAGES - 1;
    for (int kb = 0; kb < nkb; kb++) {
        CP_WAIT(STAGES - 2);
        __syncthreads();
        if (kb + STAGES - 1 < nkb) issue(kb + STAGES - 1, wslot);
        CP_COMMIT();
        if (++wslot == STAGES) wslot = 0;

        const uint32_t sbs = sb0 + rslot * STAGE_B;
#pragma unroll
        for (int ks = 0; ks < 4; ks++) {
            uint32_t afr[2][4];
#pragma unroll
            for (int mi = 0; mi < 2; mi++)
                ldsm4(afr[mi][0], afr[mi][1], afr[mi][2], afr[mi][3],
                      sbs + aoff[mi] + ks * 32);
            uint32_t bfr[NFR][2];
            uint32_t bfr2[DUAL ? NFR : 1][2];
#pragma unroll
            for (int p = 0; p < NPAIR; p++) {
                uint32_t r0, r1, r2, r3;
                ldsm4(r0, r1, r2, r3, sbs + boff[p] + ks * 32);
                bfr[2 * p][0] = r0; bfr[2 * p][1] = r1;
                bfr[2 * p + 1][0] = r2; bfr[2 * p + 1][1] = r3;
                if (DUAL) {
                    ldsm4(r0, r1, r2, r3, sbs + boff[p] + B2OFF + ks * 32);
                    bfr2[2 * p][0] = r0; bfr2[2 * p][1] = r1;
                    bfr2[2 * p + 1][0] = r2; bfr2[2 * p + 1][1] = r3;
                }
            }
#pragma unroll
            for (int mi = 0; mi < 2; mi++)
#pragma unroll
                for (int ni = 0; ni < NFR; ni++) {
                    mma_f16(acc[mi][ni], afr[mi], bfr[ni]);
                    if (DUAL) mma_f16(acc2[mi][ni], afr[mi], bfr2[ni]);
                }
        }
        if (++rslot == STAGES) rslot = 0;
    }

    // -------- epilogue --------
    if constexpr (EPI == 2) {
        // fused chunk-local scan for the Bu GEMM (BN=128, N=512)
        CP_WAIT(0);
        __syncthreads();
        float* St = reinterpret_cast<float*>(smemh);
        constexpr int RSO = 136;                      // conflict-free fp32 row stride
#pragma unroll
        for (int mi = 0; mi < 2; mi++) {
            int r0 = warp_m * 32 + mi * 16 + g;
#pragma unroll
            for (int ni = 0; ni < NFR; ni++) {
                int c = warp_n * WN + ni * 8 + tig * 2;
                *(float2*)&St[r0 * RSO + c]       = make_float2(acc[mi][ni][0], acc[mi][ni][1]);
                *(float2*)&St[(r0 + 8) * RSO + c] = make_float2(acc[mi][ni][2], acc[mi][ni][3]);
            }
        }
        __syncthreads();
        const int sl = tid & 63;                      // local complex state
        const int ch4 = tid >> 6;                     // chunk within tile (0..3)
        const int sglob = (bn >> 1) + sl;
        const float2 l = lamp[sglob];
        const int b = bm / SEQ;
        const int chb = ((bm % SEQ) >> 5) + ch4;
        float hr = 0.f, hi = 0.f;
        float2* outp = (float2*)Cf;
        const size_t rowbase = (size_t)(bm + ch4 * 32);
#pragma unroll 4
        for (int i = 0; i < 32; i++) {
            float2 u = *(float2*)&St[(ch4 * 32 + i) * RSO + sl * 2];
            float nr = fmaf(l.x, hr, fmaf(-l.y, hi, u.x));
            float ni2 = fmaf(l.x, hi, fmaf( l.y, hr, u.y));
            hr = nr; hi = ni2;
            outp[(rowbase + i) * STATE + sglob] = make_float2(hr, hi);
        }
        g_carry[(b * NCH + chb) * STATE + sglob] = make_float2(hr, hi);
        return;
    }

#pragma unroll
    for (int mi = 0; mi < 2; mi++) {
        int row0 = bm + warp_m * 32 + mi * 16 + g;
        int row1 = row0 + 8;
#pragma unroll
        for (int ni = 0; ni < NFR; ni++) {
            int col = bn + warp_n * WN + ni * 8 + tig * 2;
            size_t o0 = (size_t)row0 * N + col;
            size_t o1 = (size_t)row1 * N + col;
            float r0 = acc[mi][ni][0], r1 = acc[mi][ni][1];
            float r2 = acc[mi][ni][2], r3 = acc[mi][ni][3];
            float2 v0, v1;
            if (DUAL) {
                float b10 = bias[col], b11 = bias[col + 1];
                float b20 = bias2[col], b21 = bias2[col + 1];
                float q0 = acc2[mi][ni][0], q1 = acc2[mi][ni][1];
                float q2 = acc2[mi][ni][2], q3 = acc2[mi][ni][3];
                float s0 = 1.f / (1.f + expf(-(q0 + b20)));
                float s1 = 1.f / (1.f + expf(-(q1 + b21)));
                float s2 = 1.f / (1.f + expf(-(q2 + b20)));
                float s3 = 1.f / (1.f + expf(-(q3 + b21)));
                v0 = make_float2(fmaf(r0 + b10, s0, e1[o0]), fmaf(r1 + b11, s1, e1[o0 + 1]));
                v1 = make_float2(fmaf(r2 + b10, s2, e1[o1]), fmaf(r3 + b11, s3, e1[o1 + 1]));
            } else if (EPI == 0) {
                float b0 = bias ? bias[col] : 0.f;
                float b1 = bias ? bias[col + 1] : 0.f;
                v0 = make_float2(r0 + b0, r1 + b1);
                v1 = make_float2(r2 + b0, r3 + b1);
            } else {
                float d0 = e2[col], d1 = e2[col + 1];
                float2 h0 = __half22float2(*(const __half2*)(e1h + o0));
                float2 h1 = __half22float2(*(const __half2*)(e1h + o1));
                float t0 = r0 + h0.x * d0;
                float t1 = r1 + h0.y * d1;
                float t2 = r2 + h1.x * d0;
                float t3 = r3 + h1.y * d1;
                v0 = make_float2(t0 * normcdff(t0), t1 * normcdff(t1));
                v1 = make_float2(t2 * normcdff(t2), t3 * normcdff(t3));
            }
            if (Cf) {
                *(float2*)(Cf + o0) = v0;
                *(float2*)(Cf + o1) = v1;
            }
            if (C16) {
                *(__half2*)(C16 + o0) = __floats2half2_rn(v0.x, v0.y);
                *(__half2*)(C16 + o1) = __floats2half2_rn(v1.x, v1.y);
            }
        }
    }
}

// ---------------- launcher ----------------
extern "C" void kernel_launch(void* const* d_in, const int* in_sizes, int n_in,
                              void* d_out, int out_size)
{
    const float* x    = (const float*)d_in[0];
    const float* embW = (const float*)d_in[1];
    const float* embb = (const float*)d_in[2];
    const float* nu   = (const float*)d_in[3];
    const float* th   = (const float*)d_in[4];
    const float* ga   = (const float*)d_in[5];
    const float* Bre  = (const float*)d_in[6];
    const float* Bim  = (const float*)d_in[7];
    const float* Cre  = (const float*)d_in[8];
    const float* Cim  = (const float*)d_in[9];
    const float* Dv   = (const float*)d_in[10];
    const float* W1   = (const float*)d_in[11];
    const float* b1   = (const float*)d_in[12];
    const float* W2   = (const float*)d_in[13];
    const float* b2   = (const float*)d_in[14];
    const float* outW = (const float*)d_in[15];
    const float* outb = (const float*)d_in[16];
    float* out = (float*)d_out;
    (void)in_sizes; (void)n_in; (void)out_size;

    float *bufh, *bufa;
    float2* lam2;
    __half *h16, *y16, *hs16, *x16, *Bn, *Wc, *W1h, *W2h, *embWh, *outWh;
    cudaGetSymbolAddress((void**)&bufh, g_bufh);
    cudaGetSymbolAddress((void**)&bufa, g_bufa);
    cudaGetSymbolAddress((void**)&lam2, g_lam2);
    cudaGetSymbolAddress((void**)&h16,  g_h16);
    cudaGetSymbolAddress((void**)&y16,  g_y16);
    cudaGetSymbolAddress((void**)&hs16, g_hs16);
    cudaGetSymbolAddress((void**)&x16,  g_x16);
    cudaGetSymbolAddress((void**)&Bn,   g_Bn);
    cudaGetSymbolAddress((void**)&Wc,   g_Wc);
    cudaGetSymbolAddress((void**)&W1h,  g_W1h);
    cudaGetSymbolAddress((void**)&W2h,  g_W2h);
    cudaGetSymbolAddress((void**)&embWh, g_embWh);
    cudaGetSymbolAddress((void**)&outWh, g_outWh);

    const int SM_MAIN = (128 + 128) * 72 * 3 * 2;   // 110592
    const int SM_OUT  = (128 + 64) * 72 * 3 * 2;    // 82944
    cudaFuncSetAttribute(mma_gemm<128, 0, false>, cudaFuncAttributeMaxDynamicSharedMemorySize, SM_MAIN);
    cudaFuncSetAttribute(mma_gemm<128, 1, false>, cudaFuncAttributeMaxDynamicSharedMemorySize, SM_MAIN);
    cudaFuncSetAttribute(mma_gemm<128, 2, false>, cudaFuncAttributeMaxDynamicSharedMemorySize, SM_MAIN);
    cudaFuncSetAttribute(mma_gemm<64,  0, true >, cudaFuncAttributeMaxDynamicSharedMemorySize, SM_MAIN);
    cudaFuncSetAttribute(mma_gemm<64,  0, false>, cudaFuncAttributeMaxDynamicSharedMemorySize, SM_OUT);

    const int M = MROWS;
    dim3 blk(256);
    dim3 g512(HIDDEN / 128, M / 128);     // (4, 256)
    dim3 gdual(HIDDEN / 64, M / 128);     // (8, 256)
    dim3 gout(1, M / 128);

    prep_all_kernel<<<512, 256>>>(x, embW, outW, nu, th, ga, Bre, Bim, Cre, Cim, W1, W2);

    // embedding: h = x @ embW^T + embb  -> bufh (fp32) + h16
    mma_gemm<128, 0, false><<<g512, blk, SM_MAIN>>>(
        x16, embWh, nullptr, embb, nullptr, bufh, h16, M, HIDDEN, DIN,
        nullptr, nullptr, nullptr, nullptr);

    for (int l = 0; l < NLAYERS; l++) {
        const float2* lamp = lam2 + l * STATE;

        // Bu = h @ Bn^T, fused chunk-local scan -> bufa (local) + g_carry
        mma_gemm<128, 2, false><<<g512, blk, SM_MAIN>>>(
            h16, Bn + (size_t)l * 2 * STATE * HIDDEN, nullptr, nullptr, nullptr,
            bufa, nullptr, M, 2 * STATE, HIDDEN, nullptr, nullptr, nullptr, lamp);

        // combine carries, then correct local -> hs16
        scanB_kernel<<<16, 256>>>(lamp);
        scanC_kernel<<<1024, 256>>>(bufa, hs16, lamp);

        // y = gelu( Hs @ Wc^T + h*D ) -> y16
        mma_gemm<128, 1, false><<<g512, blk, SM_MAIN>>>(
            hs16, Wc + (size_t)l * HIDDEN * 2 * STATE, nullptr, nullptr, nullptr,
            nullptr, y16, M, HIDDEN, 2 * STATE, nullptr, h16, Dv + l * HIDDEN, nullptr);

        // h = (y@W1 + b1) * sigmoid(y@W2 + b2) + h  -> bufh (fp32) + h16
        mma_gemm<64, 0, true><<<gdual, blk, SM_MAIN>>>(
            y16, W1h + (size_t)l * HIDDEN * HIDDEN, W2h + (size_t)l * HIDDEN * HIDDEN,
            b1 + l * HIDDEN, b2 + l * HIDDEN, bufh, h16,
            M, HIDDEN, HIDDEN, bufh, nullptr, nullptr, nullptr);
    }

    // out = h @ outW^T + outb
    mma_gemm<64, 0, false><<<gout, blk, SM_OUT>>>(
        h16, outWh, nullptr, outb, nullptr, out, nullptr, M, DOUT, HIDDEN,
        nullptr, nullptr, nullptr, nullptr);
}

// round 16
// speedup vs baseline: 11.7570x; 1.0600x over previous
#include <cuda_runtime.h>
#include <cuda_fp16.h>
#include <cstdint>
#include <math.h>

#define BATCH   16
#define SEQ     2048
#define DIN     128
#define HIDDEN  512
#define STATE   256
#define DOUT    64
#define NLAYERS 4
#define MROWS   (BATCH * SEQ)   /* 32768 */
#define NCH     64
#define CLEN    (SEQ / NCH)     /* 32 */

// ---------------- scratch (allocation-free: __device__ globals) ----------------
__device__ float  g_bufh[(size_t)MROWS * HIDDEN];            // residual stream h (fp32)
__device__ float  g_bufa[(size_t)MROWS * HIDDEN];            // local-scan output (fp32)
__device__ __align__(16) __half g_h16 [(size_t)MROWS * HIDDEN];  // h   (GEMM A)
__device__ __align__(16) __half g_y16 [(size_t)MROWS * HIDDEN];  // y   (GEMM A)
__device__ __align__(16) __half g_hs16[(size_t)MROWS * HIDDEN];  // Hs  (GEMM A)
__device__ __align__(16) __half g_x16 [(size_t)MROWS * DIN];     // x   (GEMM A)
__device__ __align__(16) __half g_Bn [(size_t)NLAYERS * 2 * STATE * HIDDEN];
__device__ __align__(16) __half g_Wc [(size_t)NLAYERS * HIDDEN * 2 * STATE];
__device__ __align__(16) __half g_W1h[(size_t)NLAYERS * HIDDEN * HIDDEN];
__device__ __align__(16) __half g_W2h[(size_t)NLAYERS * HIDDEN * HIDDEN];
__device__ __align__(16) __half g_embWh[HIDDEN * DIN];
__device__ __align__(16) __half g_outWh[DOUT * HIDDEN];
__device__ float2 g_lam2[NLAYERS * STATE];
__device__ float2 g_carry[BATCH * NCH * STATE];
__device__ float2 g_cin  [BATCH * NCH * STATE];

// ---------------- mma helpers ----------------
__device__ __forceinline__ void mma_f16(float* d, const uint32_t* a, const uint32_t* b) {
    asm volatile(
        "mma.sync.aligned.m16n8k16.row.col.f32.f16.f16.f32 "
        "{%0,%1,%2,%3}, {%4,%5,%6,%7}, {%8,%9}, {%0,%1,%2,%3};"
        : "+f"(d[0]), "+f"(d[1]), "+f"(d[2]), "+f"(d[3])
        : "r"(a[0]), "r"(a[1]), "r"(a[2]), "r"(a[3]), "r"(b[0]), "r"(b[1]));
}
__device__ __forceinline__ void ldsm4(uint32_t& r0, uint32_t& r1, uint32_t& r2, uint32_t& r3,
                                      uint32_t addr) {
    asm volatile("ldmatrix.sync.aligned.m8n8.x4.shared.b16 {%0,%1,%2,%3}, [%4];"
        : "=r"(r0), "=r"(r1), "=r"(r2), "=r"(r3) : "r"(addr));
}
__device__ __forceinline__ void cp16(void* s, const void* g) {
    uint32_t sa = (uint32_t)__cvta_generic_to_shared(s);
    asm volatile("cp.async.cg.shared.global [%0], [%1], 16;" :: "r"(sa), "l"(g));
}
#define CP_COMMIT() asm volatile("cp.async.commit_group;" ::: "memory")
#define CP_WAIT(n)  asm volatile("cp.async.wait_group %0;" :: "n"(n) : "memory")

// ---------------- one-time conversions (all layers) ----------------
__global__ void prep_all_kernel(const float* __restrict__ x,
                                const float* __restrict__ embW,
                                const float* __restrict__ outW,
                                const float* __restrict__ nu, const float* __restrict__ th,
                                const float* __restrict__ ga,
                                const float* __restrict__ Bre, const float* __restrict__ Bim,
                                const float* __restrict__ Cre, const float* __restrict__ Cim,
                                const float* __restrict__ W1, const float* __restrict__ W2)
{
    int tid = blockIdx.x * blockDim.x + threadIdx.x;
    int stride = gridDim.x * blockDim.x;
    for (int i = tid; i < MROWS * DIN; i += stride) g_x16[i] = __float2half_rn(x[i]);
    for (int i = tid; i < HIDDEN * DIN; i += stride) g_embWh[i] = __float2half_rn(embW[i]);
    for (int i = tid; i < DOUT * HIDDEN; i += stride) g_outWh[i] = __float2half_rn(outW[i]);
    for (int i = tid; i < NLAYERS * STATE; i += stride) {
        float mag = expf(-expf(nu[i]));
        float ang = expf(th[i]);
        g_lam2[i] = make_float2(mag * cosf(ang), mag * sinf(ang));
    }
    for (int idx = tid; idx < NLAYERS * STATE * HIDDEN; idx += stride) {
        int l = idx / (STATE * HIDDEN);
        int r = idx % (STATE * HIDDEN);
        int s = r / HIDDEN, h = r % HIDDEN;
        float g = expf(ga[l * STATE + s]);
        size_t base = (size_t)l * 2 * STATE * HIDDEN;
        g_Bn[base + (size_t)(2 * s)     * HIDDEN + h] = __float2half_rn(Bre[idx] * g);
        g_Bn[base + (size_t)(2 * s + 1) * HIDDEN + h] = __float2half_rn(Bim[idx] * g);
    }
    for (int idx = tid; idx < NLAYERS * HIDDEN * STATE; idx += stride) {
        int l = idx / (HIDDEN * STATE);
        int r = idx % (HIDDEN * STATE);
        int h = r / STATE, s = r % STATE;
        size_t base = (size_t)l * HIDDEN * 2 * STATE;
        g_Wc[base + (size_t)h * (2 * STATE) + 2 * s]     = __float2half_rn( Cre[idx]);
        g_Wc[base + (size_t)h * (2 * STATE) + 2 * s + 1] = __float2half_rn(-Cim[idx]);
    }
    for (int idx = tid; idx < NLAYERS * HIDDEN * HIDDEN; idx += stride) {
        g_W1h[idx] = __float2half_rn(W1[idx]);
        g_W2h[idx] = __float2half_rn(W2[idx]);
    }
}

// ---------------- carry combine across chunks (smem-staged, MLP loads) ----------------
// grid (BATCH, STATE/64), block 256
__global__ void scanB_kernel(const float2* __restrict__ lamp)
{
    __shared__ float2 sc[NCH][64];                   // 64 chunks x 64 states = 32 KB
    const int b = blockIdx.x;
    const int sg = blockIdx.y * 64;
#pragma unroll
    for (int i = 0; i < NCH * 64 / 256; i++) {       // 16 independent coalesced loads
        int idx = threadIdx.x + i * 256;
        int ch = idx >> 6, s = idx & 63;
        sc[ch][s] = g_carry[(b * NCH + ch) * STATE + sg + s];
    }
    __syncthreads();
    if (threadIdx.x < 64) {
        const int s = threadIdx.x;
        float2 l = lamp[sg + s];
        float pr = l.x, pi = l.y;
#pragma unroll
        for (int k = 0; k < 5; k++) {                // lam^32
            float nr = pr * pr - pi * pi;
            float ni = 2.f * pr * pi;
            pr = nr; pi = ni;
        }
        float hr = 0.f, hi = 0.f;
#pragma unroll
        for (int ch = 0; ch < NCH; ch++) {
            g_cin[(b * NCH + ch) * STATE + sg + s] = make_float2(hr, hi);
            float2 c = sc[ch][s];
            float nr = pr * hr - pi * hi + c.x;
            float ni = pr * hi + pi * hr + c.y;
            hr = nr; hi = ni;
        }
    }
}

// ---------------- carry correction: Hs_t = local_t + lam^{i+1} * H_in ----------------
__global__ void scanC_kernel(const float* __restrict__ local, __half* __restrict__ Hs16,
                             const float2* __restrict__ lamp)
{
    int t = blockIdx.x * blockDim.x + threadIdx.x;
    int s  = t & (STATE - 1);
    int ch = (t >> 8) & (NCH - 1);
    int b  = t >> 14;
    float2 l = lamp[s];
    size_t base = ((size_t)(b * SEQ + ch * CLEN)) * STATE + s;
    const float2* src = (const float2*)local + base;
    __half2* dst = (__half2*)Hs16 + base;
    float2 H = g_cin[(b * NCH + ch) * STATE + s];
    float cpr = l.x, cpi = l.y;                      // lam^1
#pragma unroll 4
    for (int i = 0; i < CLEN; i++) {
        float2 lo = src[(size_t)i * STATE];
        float hr = lo.x + cpr * H.x - cpi * H.y;
        float hi = lo.y + cpr * H.y + cpi * H.x;
        dst[(size_t)i * STATE] = __floats2half2_rn(hr, hi);
        float nr = cpr * l.x - cpi * l.y;
        cpi = cpr * l.y + cpi * l.x;
        cpr = nr;
    }
}

// ---------------- pipelined fp16 MMA GEMM: C = A @ W^T (+ epilogue) ----------------
// EPI 0: v = acc (+bias[col])
// EPI 1: v = gelu_exact(acc + e1h[o]*e2[col])
// EPI 2: fused chunk-local scan (Bu GEMM): local scan -> Cf (float2), carries -> g_carry
// DUAL : v = (acc+bias) * sigmoid(acc2+bias2) + e1[o]
template <int BN, int EPI, bool DUAL>
__global__ void __launch_bounds__(256, 2)
mma_gemm(const __half* __restrict__ A, const __half* __restrict__ W,
         const __half* __restrict__ W2p,
         const float* __restrict__ bias, const float* __restrict__ bias2,
         float* __restrict__ Cf, __half* __restrict__ C16,
         int M, int N, int K,
         const float* __restrict__ e1, const __half* __restrict__ e1h,
         const float* __restrict__ e2, const float2* __restrict__ lamp)
{
    constexpr int BM = 128, BK = 64, RS = BK + 8;     // row stride = 72 halves (144 B)
    constexpr int STAGES = 3;
    constexpr int WN = BN / 2, NFR = WN / 8, NPAIR = NFR / 2;
    constexpr int NBTILE = DUAL ? 2 * BN : BN;
    constexpr int STAGE_H = (BM + NBTILE) * RS;       // halves per stage
    constexpr int STAGE_B = STAGE_H * 2;              // bytes per stage
    constexpr int BCH = BN / 32;

    extern __shared__ __half smemh[];

    const int tid = threadIdx.x;
    const int wid = tid >> 5, lane = tid & 31;
    const int g = lane >> 2, tig = lane & 3;
    const int warp_m = wid & 3, warp_n = wid >> 2;    // 4 x 2
    const int bm = blockIdx.y * BM;
    const int bn = blockIdx.x * BN;

    const int t8 = lane >> 3, w8 = lane & 7;
    const uint32_t sb0 = (uint32_t)__cvta_generic_to_shared(smemh);
    const int arow = warp_m * 32 + (t8 & 1) * 8 + w8;
    uint32_t aoff[2];
    aoff[0] = (uint32_t)((arow * RS + (t8 >> 1) * 8) * 2);
    aoff[1] = aoff[0] + 16 * RS * 2;
    uint32_t boff[NPAIR];
#pragma unroll
    for (int p = 0; p < NPAIR; p++) {
        int col = warp_n * WN + p * 16 + (t8 >> 1) * 8 + w8;
        boff[p] = (uint32_t)(((BM + col) * RS + (t8 & 1) * 8) * 2);
    }
    constexpr uint32_t B2OFF = (uint32_t)(BN * RS * 2);

    float acc[2][NFR][4];
    float acc2[DUAL ? 2 : 1][DUAL ? NFR : 1][4];
#pragma unroll
    for (int mi = 0; mi < 2; mi++)
#pragma unroll
        for (int ni = 0; ni < NFR; ni++)
#pragma unroll
            for (int j = 0; j < 4; j++) {
                acc[mi][ni][j] = 0.f;
                if (DUAL) acc2[mi][ni][j] = 0.f;
            }

    const int nkb = K / BK;

    auto issue = [&](int kb, int slot) {
        __half* Sb = smemh + slot * STAGE_H;
        const __half* Ag = A + (size_t)bm * K + kb * BK;
#pragma unroll
        for (int i = 0; i < 4; i++) {
            int c = tid + i * 256;
            int r = c >> 3, kc = c & 7;
            cp16(Sb + r * RS + kc * 8, Ag + (size_t)r * K + kc * 8);
        }
        const __half* Wg = W + (size_t)bn * K + kb * BK;
        __half* Bb = Sb + BM * RS;
#pragma unroll
        for (int i = 0; i < BCH; i++) {
            int c = tid + i * 256;
            int r = c >> 3, kc = c & 7;
            cp16(Bb + r * RS + kc * 8, Wg + (size_t)r * K + kc * 8);
        }
        if (DUAL) {
            const __half* W2g = W2p + (size_t)bn * K + kb * BK;
            __half* B2b = Sb + (BM + BN) * RS;
#pragma unroll
            for (int i = 0; i < BCH; i++) {
                int c = tid + i * 256;
                int r = c >> 3, kc = c & 7;
                cp16(B2b + r * RS + kc * 8, W2g + (size_t)r * K + kc * 8);
            }
        }
    };

#pragma unroll
    for (int s = 0; s < STAGES - 1; s++) {
        if (s < nkb) issue(s, s);
        CP_COMMIT();
    }

    int rslot = 0, wslot = STAGES - 1;
    for (int kb = 0; kb < nkb; kb++) {
        CP_WAIT(STAGES - 2);
        __syncthreads();
        if (kb + STAGES - 1 < nkb) issue(kb + STAGES - 1, wslot);
        CP_COMMIT();
        if (++wslot == STAGES) wslot = 0;

        const uint32_t sbs = sb0 + rslot * STAGE_B;
#pragma unroll
        for (int ks = 0; ks < 4; ks++) {
            uint32_t afr[2][4];
#pragma unroll
            for (int mi = 0; mi < 2; mi++)
                ldsm4(afr[mi][0], afr[mi][1], afr[mi][2], afr[mi][3],
                      sbs + aoff[mi] + ks * 32);
            uint32_t bfr[NFR][2];
            uint32_t bfr2[DUAL ? NFR : 1][2];
#pragma unroll
            for (int p = 0; p < NPAIR; p++) {
                uint32_t r0, r1, r2, r3;
                ldsm4(r0, r1, r2, r3, sbs + boff[p] + ks * 32);
                bfr[2 * p][0] = r0; bfr[2 * p][1] = r1;
                bfr[2 * p + 1][0] = r2; bfr[2 * p + 1][1] = r3;
                if (DUAL) {
                    ldsm4(r0, r1, r2, r3, sbs + boff[p] + B2OFF + ks * 32);
                    bfr2[2 * p][0] = r0; bfr2[2 * p][1] = r1;
                    bfr2[2 * p + 1][0] = r2; bfr2[2 * p + 1][1] = r3;
                }
            }
#pragma unroll
            for (int mi = 0; mi < 2; mi++)
#pragma unroll
                for (int ni = 0; ni < NFR; ni++) {
                    mma_f16(acc[mi][ni], afr[mi], bfr[ni]);
                    if (DUAL) mma_f16(acc2[mi][ni], afr[mi], bfr2[ni]);
                }
        }
        if (++rslot == STAGES) rslot = 0;
    }

    // -------- epilogue --------
    if constexpr (EPI == 2) {
        // fused chunk-local scan for the Bu GEMM (BN=128, N=512)
        CP_WAIT(0);
        __syncthreads();
        float* St = reinterpret_cast<float*>(smemh);
        constexpr int RSO = 136;                      // conflict-free fp32 row stride
#pragma unroll
        for (int mi = 0; mi < 2; mi++) {
            int r0 = warp_m * 32 + mi * 16 + g;
#pragma unroll
            for (int ni = 0; ni < NFR; ni++) {
                int c = warp_n * WN + ni * 8 + tig * 2;
                *(float2*)&St[r0 * RSO + c]       = make_float2(acc[mi][ni][0], acc[mi][ni][1]);
                *(float2*)&St[(r0 + 8) * RSO + c] = make_float2(acc[mi][ni][2], acc[mi][ni][3]);
            }
        }
        __syncthreads();
        const int sl = tid & 63;                      // local complex state
        const int ch4 = tid >> 6;                     // chunk within tile (0..3)
        const int sglob = (bn >> 1) + sl;
        const float2 l = lamp[sglob];
        const int b = bm / SEQ;
        const int chb = ((bm % SEQ) >> 5) + ch4;
        float hr = 0.f, hi = 0.f;
        float2* outp = (float2*)Cf;
        const size_t rowbase = (size_t)(bm + ch4 * 32);
#pragma unroll 4
        for (int i = 0; i < 32; i++) {
            float2 u = *(float2*)&St[(ch4 * 32 + i) * RSO + sl * 2];
            float nr = fmaf(l.x, hr, fmaf(-l.y, hi, u.x));
            float ni2 = fmaf(l.x, hi, fmaf( l.y, hr, u.y));
            hr = nr; hi = ni2;
            outp[(rowbase + i) * STATE + sglob] = make_float2(hr, hi);
        }
        g_carry[(b * NCH + chb) * STATE + sglob] = make_float2(hr, hi);
        return;
    }

#pragma unroll
    for (int mi = 0; mi < 2; mi++) {
        int row0 = bm + warp_m * 32 + mi * 16 + g;
        int row1 = row0 + 8;
#pragma unroll
        for (int ni = 0; ni < NFR; ni++) {
            int col = bn + warp_n * WN + ni * 8 + tig * 2;
            size_t o0 = (size_t)row0 * N + col;
            size_t o1 = (size_t)row1 * N + col;
            float r0 = acc[mi][ni][0], r1 = acc[mi][ni][1];
            float r2 = acc[mi][ni][2], r3 = acc[mi][ni][3];
            float2 v0, v1;
            if (DUAL) {
                float b10 = bias[col], b11 = bias[col + 1];
                float b20 = bias2[col], b21 = bias2[col + 1];
                float q0 = acc2[mi][ni][0], q1 = acc2[mi][ni][1];
                float q2 = acc2[mi][ni][2], q3 = acc2[mi][ni][3];
                float s0 = 1.f / (1.f + expf(-(q0 + b20)));
                float s1 = 1.f / (1.f + expf(-(q1 + b21)));
                float s2 = 1.f / (1.f + expf(-(q2 + b20)));
                float s3 = 1.f / (1.f + expf(-(q3 + b21)));
                v0 = make_float2(fmaf(r0 + b10, s0, e1[o0]), fmaf(r1 + b11, s1, e1[o0 + 1]));
                v1 = make_float2(fmaf(r2 + b10, s2, e1[o1]), fmaf(r3 + b11, s3, e1[o1 + 1]));
            } else if (EPI == 0) {
                float b0 = bias ? bias[col] : 0.f;
                float b1 = bias ? bias[col + 1] : 0.f;
                v0 = make_float2(r0 + b0, r1 + b1);
                v1 = make_float2(r2 + b0, r3 + b1);
            } else {
                float d0 = e2[col], d1 = e2[col + 1];
                float2 h0 = __half22float2(*(const __half2*)(e1h + o0));
                float2 h1 = __half22float2(*(const __half2*)(e1h + o1));
                float t0 = r0 + h0.x * d0;
                float t1 = r1 + h0.y * d1;
                float t2 = r2 + h1.x * d0;
                float t3 = r3 + h1.y * d1;
                v0 = make_float2(t0 * normcdff(t0), t1 * normcdff(t1));
                v1 = make_float2(t2 * normcdff(t2), t3 * normcdff(t3));
            }
            if (Cf) {
                *(float2*)(Cf + o0) = v0;
                *(float2*)(Cf + o1) = v1;
            }
            if (C16) {
                *(__half2*)(C16 + o0) = __floats2half2_rn(v0.x, v0.y);
                *(__half2*)(C16 + o1) = __floats2half2_rn(v1.x, v1.y);
            }
        }
    }
}

// ---------------- launcher ----------------
extern "C" void kernel_launch(void* const* d_in, const int* in_sizes, int n_in,
                              void* d_out, int out_size)
{
    const float* x    = (const float*)d_in[0];
    const float* embW = (const float*)d_in[1];
    const float* embb = (const float*)d_in[2];
    const float* nu   = (const float*)d_in[3];
    const float* th   = (const float*)d_in[4];
    const float* ga   = (const float*)d_in[5];
    const float* Bre  = (const float*)d_in[6];
    const float* Bim  = (const float*)d_in[7];
    const float* Cre  = (const float*)d_in[8];
    const float* Cim  = (const float*)d_in[9];
    const float* Dv   = (const float*)d_in[10];
    const float* W1   = (const float*)d_in[11];
    const float* b1   = (const float*)d_in[12];
    const float* W2   = (const float*)d_in[13];
    const float* b2   = (const float*)d_in[14];
    const float* outW = (const float*)d_in[15];
    const float* outb = (const float*)d_in[16];
    float* out = (float*)d_out;
    (void)in_sizes; (void)n_in; (void)out_size;

    float *bufh, *bufa;
    float2* lam2;
    __half *h16, *y16, *hs16, *x16, *Bn, *Wc, *W1h, *W2h, *embWh, *outWh;
    cudaGetSymbolAddress((void**)&bufh, g_bufh);
    cudaGetSymbolAddress((void**)&bufa, g_bufa);
    cudaGetSymbolAddress((void**)&lam2, g_lam2);
    cudaGetSymbolAddress((void**)&h16,  g_h16);
    cudaGetSymbolAddress((void**)&y16,  g_y16);
    cudaGetSymbolAddress((void**)&hs16, g_hs16);
    cudaGetSymbolAddress((void**)&x16,  g_x16);
    cudaGetSymbolAddress((void**)&Bn,   g_Bn);
    cudaGetSymbolAddress((void**)&Wc,   g_Wc);
    cudaGetSymbolAddress((void**)&W1h,  g_W1h);
    cudaGetSymbolAddress((void**)&W2h,  g_W2h);
    cudaGetSymbolAddress((void**)&embWh, g_embWh);
    cudaGetSymbolAddress((void**)&outWh, g_outWh);

    const int SM_MAIN = (128 + 128) * 72 * 3 * 2;   // 110592
    const int SM_OUT  = (128 + 64) * 72 * 3 * 2;    // 82944
    cudaFuncSetAttribute(mma_gemm<128, 0, false>, cudaFuncAttributeMaxDynamicSharedMemorySize, SM_MAIN);
    cudaFuncSetAttribute(mma_gemm<128, 1, false>, cudaFuncAttributeMaxDynamicSharedMemorySize, SM_MAIN);
    cudaFuncSetAttribute(mma_gemm<128, 2, false>, cudaFuncAttributeMaxDynamicSharedMemorySize, SM_MAIN);
    cudaFuncSetAttribute(mma_gemm<64,  0, true >, cudaFuncAttributeMaxDynamicSharedMemorySize, SM_MAIN);
    cudaFuncSetAttribute(mma_gemm<64,  0, false>, cudaFuncAttributeMaxDynamicSharedMemorySize, SM_OUT);

    const int M = MROWS;
    dim3 blk(256);
    dim3 g512(HIDDEN / 128, M / 128);     // (4, 256)
    dim3 gdual(HIDDEN / 64, M / 128);     // (8, 256)
    dim3 gout(1, M / 128);
    dim3 gscanB(BATCH, STATE / 64);       // (16, 4)

    prep_all_kernel<<<512, 256>>>(x, embW, outW, nu, th, ga, Bre, Bim, Cre, Cim, W1, W2);

    // embedding: h = x @ embW^T + embb  -> bufh (fp32) + h16
    mma_gemm<128, 0, false><<<g512, blk, SM_MAIN>>>(
        x16, embWh, nullptr, embb, nullptr, bufh, h16, M, HIDDEN, DIN,
        nullptr, nullptr, nullptr, nullptr);

    for (int l = 0; l < NLAYERS; l++) {
        const float2* lamp = lam2 + l * STATE;

        // Bu = h @ Bn^T, fused chunk-local scan -> bufa (local) + g_carry
        mma_gemm<128, 2, false><<<g512, blk, SM_MAIN>>>(
            h16, Bn + (size_t)l * 2 * STATE * HIDDEN, nullptr, nullptr, nullptr,
            bufa, nullptr, M, 2 * STATE, HIDDEN, nullptr, nullptr, nullptr, lamp);

        // combine carries (smem-staged), then correct local -> hs16
        scanB_kernel<<<gscanB, 256>>>(lamp);
        scanC_kernel<<<1024, 256>>>(bufa, hs16, lamp);

        // y = gelu( Hs @ Wc^T + h*D ) -> y16
        mma_gemm<128, 1, false><<<g512, blk, SM_MAIN>>>(
            hs16, Wc + (size_t)l * HIDDEN * 2 * STATE, nullptr, nullptr, nullptr,
            nullptr, y16, M, HIDDEN, 2 * STATE, nullptr, h16, Dv + l * HIDDEN, nullptr);

        // h = (y@W1 + b1) * sigmoid(y@W2 + b2) + h  -> bufh (fp32) + h16
        mma_gemm<64, 0, true><<<gdual, blk, SM_MAIN>>>(
            y16, W1h + (size_t)l * HIDDEN * HIDDEN, W2h + (size_t)l * HIDDEN * HIDDEN,
            b1 + l * HIDDEN, b2 + l * HIDDEN, bufh, h16,
            M, HIDDEN, HIDDEN, bufh, nullptr, nullptr, nullptr);
    }

    // out = h @ outW^T + outb
    mma_gemm<64, 0, false><<<gout, blk, SM_OUT>>>(
        h16, outWh, nullptr, outb, nullptr, out, nullptr, M, DOUT, HIDDEN,
        nullptr, nullptr, nullptr, nullptr);
}